// round 11
// baseline (speedup 1.0000x reference)
#include <cuda_runtime.h>
#include <cuda_bf16.h>
#include <cstdint>

// Problem constants
#define BATCH   2
#define S_LEN   2048
#define D_MODEL 1024
#define NH      16
#define HD      64
#define WINDOW  256
#define TOKENS  (BATCH * S_LEN)               // 4096
#define OUT_ELEMS ((size_t)TOKENS * D_MODEL)  // 4194304
#define KEFF    3072                          // 3 * 1024 (hi/hi/lo split along K)
#define NCHUNK  48                            // KEFF / 64

// ---------------- device scratch (allocation-free rule) ----------------
__device__ __align__(128) float g_q [BATCH * NH * S_LEN * HD];
__device__ __align__(128) __nv_bfloat16 g_xhat[(size_t)TOKENS * KEFF];      // [A_hi|A_hi|A_lo]
__device__ __align__(128) __nv_bfloat16 g_ahat[(size_t)TOKENS * KEFF];
__device__ __align__(128) __nv_bfloat16 g_wat [(size_t)3 * D_MODEL * KEFF]; // W^T split [B_hi|B_lo|B_hi]
__device__ __align__(128) __nv_bfloat16 g_wpt [(size_t)D_MODEL * KEFF];

// ---------------- helpers ----------------
__device__ __forceinline__ uint32_t smem_u32(const void* p) {
    uint32_t a;
    asm("{ .reg .u64 t; cvta.to.shared.u64 t, %1; cvt.u32.u64 %0, t; }" : "=r"(a) : "l"(p));
    return a;
}
__device__ __forceinline__ void cp16(uint32_t saddr, const void* g) {
    asm volatile("cp.async.cg.shared.global [%0], [%1], 16;" :: "r"(saddr), "l"(g));
}
#define CP_COMMIT() asm volatile("cp.async.commit_group;" ::: "memory")
#define CP_WAIT1()  asm volatile("cp.async.wait_group 1;" ::: "memory")
#define CP_WAIT0()  asm volatile("cp.async.wait_group 0;" ::: "memory")

__device__ __forceinline__ void ldmx4(uint32_t* r, uint32_t addr) {
    asm volatile("ldmatrix.sync.aligned.m8n8.x4.shared.b16 {%0,%1,%2,%3}, [%4];"
                 : "=r"(r[0]), "=r"(r[1]), "=r"(r[2]), "=r"(r[3]) : "r"(addr));
}
__device__ __forceinline__ void mma16816(float* c, const uint32_t* a, const uint32_t* b) {
    asm volatile(
        "mma.sync.aligned.m16n8k16.row.col.f32.bf16.bf16.f32 "
        "{%0,%1,%2,%3}, {%4,%5,%6,%7}, {%8,%9}, {%0,%1,%2,%3};"
        : "+f"(c[0]), "+f"(c[1]), "+f"(c[2]), "+f"(c[3])
        : "r"(a[0]), "r"(a[1]), "r"(a[2]), "r"(a[3]), "r"(b[0]), "r"(b[1]));
}
// pack two floats to bf16x2 word (x = first arg in low half)
__device__ __forceinline__ uint32_t bf2pack(float a, float b) {
    __nv_bfloat162 t = __floats2bfloat162_rn(a, b);
    return *reinterpret_cast<uint32_t*>(&t);
}

// ---------------- split conversion kernels (vectorized) ----------------
__global__ void convA_k(const float* __restrict__ A, __nv_bfloat16* __restrict__ O, int total4)
{
    int idx = blockIdx.x * blockDim.x + threadIdx.x;
    if (idx >= total4) return;
    const int m = idx >> 8;
    const int k = (idx & 255) * 4;
    float4 v = *(const float4*)&A[(size_t)m * 1024 + k];
    float h0f = __bfloat162float(__float2bfloat16(v.x));
    float h1f = __bfloat162float(__float2bfloat16(v.y));
    float h2f = __bfloat162float(__float2bfloat16(v.z));
    float h3f = __bfloat162float(__float2bfloat16(v.w));
    uint2 H = {bf2pack(v.x, v.y), bf2pack(v.z, v.w)};
    uint2 L = {bf2pack(v.x - h0f, v.y - h1f), bf2pack(v.z - h2f, v.w - h3f)};
    __nv_bfloat16* row = O + (size_t)m * KEFF;
    *(uint2*)&row[k]        = H;
    *(uint2*)&row[1024 + k] = H;
    *(uint2*)&row[2048 + k] = L;
}
__global__ void convBt_k(const float* __restrict__ W, __nv_bfloat16* __restrict__ O, int N)
{
    __shared__ float tile[32][33];
    const int k0 = blockIdx.y * 32, n0 = blockIdx.x * 32;
    const int tx = threadIdx.x;   // 0..7
    const int ty = threadIdx.y;   // 0..31
    float4 w4 = *(const float4*)&W[(size_t)(k0 + ty) * N + n0 + tx * 4];
    tile[ty][tx * 4 + 0] = w4.x;
    tile[ty][tx * 4 + 1] = w4.y;
    tile[ty][tx * 4 + 2] = w4.z;
    tile[ty][tx * 4 + 3] = w4.w;
    __syncthreads();
    const int tid = ty * 8 + tx;
    const int nr = tid >> 3;
    const int kq = tid & 7;
    float v0 = tile[kq * 4 + 0][nr];
    float v1 = tile[kq * 4 + 1][nr];
    float v2 = tile[kq * 4 + 2][nr];
    float v3 = tile[kq * 4 + 3][nr];
    float h0 = __bfloat162float(__float2bfloat16(v0));
    float h1 = __bfloat162float(__float2bfloat16(v1));
    float h2 = __bfloat162float(__float2bfloat16(v2));
    float h3 = __bfloat162float(__float2bfloat16(v3));
    uint2 H = {bf2pack(v0, v1), bf2pack(v2, v3)};
    uint2 L = {bf2pack(v0 - h0, v1 - h1), bf2pack(v2 - h2, v3 - h3)};
    __nv_bfloat16* row = O + (size_t)(n0 + nr) * KEFF;
    const int k = k0 + kq * 4;
    *(uint2*)&row[k]        = H;
    *(uint2*)&row[1024 + k] = L;
    *(uint2*)&row[2048 + k] = H;
}

// ---------------- mma.sync GEMM (unchanged from R10) ----------------
#define TILE_BYTES  18432
#define BUF_BYTES   36864
#define GEMM_SMEM   110592

template<int MODE>
__global__ __launch_bounds__(256, 2) void gemm_mma(const __nv_bfloat16* __restrict__ A,
                                                   const __nv_bfloat16* __restrict__ Bt,
                                                   const float* __restrict__ bias,
                                                   float* __restrict__ C,
                                                   float* __restrict__ KV)
{
    extern __shared__ char smem[];
    const uint32_t sb = smem_u32(smem);
    const int tid = threadIdx.x;
    const int wid = tid >> 5, lid = tid & 31;
    const int m0 = blockIdx.y * 128, n0 = blockIdx.x * 128;
    const int mbase = (wid & 1) * 64;
    const int nbase = (wid >> 1) * 32;

    const char* Abase = (const char*)(A  + (size_t)m0 * KEFF);
    const char* Bbase = (const char*)(Bt + (size_t)n0 * KEFF);

    const uint32_t a_row_off = (uint32_t)((mbase + ((lid >> 3) & 1) * 8 + (lid & 7)) * 144
                                          + ((lid >> 4) * 8) * 2);
    const uint32_t b_row_off = (uint32_t)((nbase + ((lid >> 4) & 1) * 8 + (lid & 7)) * 144
                                          + (((lid >> 3) & 1) * 8) * 2);

    float acc[4][4][4];
#pragma unroll
    for (int mt = 0; mt < 4; mt++)
#pragma unroll
        for (int nt = 0; nt < 4; nt++)
#pragma unroll
            for (int i = 0; i < 4; i++) acc[mt][nt][i] = 0.f;

#define PREFETCH(c, buf)                                                          \
    {                                                                             \
        const size_t kbyte = (size_t)(c) * 128;                                   \
        const uint32_t abuf = sb + (buf) * BUF_BYTES;                             \
        const uint32_t bbuf = abuf + TILE_BYTES;                                  \
        _Pragma("unroll")                                                         \
        for (int i = 0; i < 4; i++) {                                             \
            int idx = tid + i * 256;                                              \
            int row = idx >> 3, seg = idx & 7;                                    \
            uint32_t so = row * 144 + seg * 16;                                   \
            cp16(abuf + so, Abase + (size_t)row * (KEFF * 2) + kbyte + seg * 16); \
            cp16(bbuf + so, Bbase + (size_t)row * (KEFF * 2) + kbyte + seg * 16); \
        }                                                                         \
    }

    PREFETCH(0, 0); CP_COMMIT();
    PREFETCH(1, 1); CP_COMMIT();

    int buf = 0;
    for (int c = 0; c < NCHUNK; c++) {
        if (c == NCHUNK - 1) { CP_WAIT0(); } else { CP_WAIT1(); }
        __syncthreads();
        if (c + 2 < NCHUNK) {
            int nbuf = buf + 2; if (nbuf >= 3) nbuf -= 3;
            PREFETCH(c + 2, nbuf);
            CP_COMMIT();
        }
        const uint32_t abuf = sb + buf * BUF_BYTES;
        const uint32_t bbuf = abuf + TILE_BYTES;
#pragma unroll
        for (int ks = 0; ks < 4; ks++) {
            const uint32_t kb = (uint32_t)ks * 32;
            uint32_t ar[4][4];
            uint32_t br[4][2];
#pragma unroll
            for (int mt = 0; mt < 4; mt++)
                ldmx4(ar[mt], abuf + a_row_off + mt * (16 * 144) + kb);
#pragma unroll
            for (int p = 0; p < 2; p++) {
                uint32_t r[4];
                ldmx4(r, bbuf + b_row_off + p * (16 * 144) + kb);
                br[p * 2][0] = r[0]; br[p * 2][1] = r[1];
                br[p * 2 + 1][0] = r[2]; br[p * 2 + 1][1] = r[3];
            }
#pragma unroll
            for (int mt = 0; mt < 4; mt++)
#pragma unroll
                for (int nt = 0; nt < 4; nt++)
                    mma16816(acc[mt][nt], ar[mt], br[nt]);
        }
        if (++buf == 3) buf = 0;
    }
#undef PREFETCH

    const int lrow = lid >> 2;
    const int lcol = (lid & 3) * 2;
#pragma unroll
    for (int mt = 0; mt < 4; mt++) {
        const int gm = m0 + mbase + mt * 16 + lrow;
#pragma unroll
        for (int nt = 0; nt < 4; nt++) {
            const int gn = n0 + nbase + nt * 8 + lcol;
            if (MODE == 0) {
                const float b0 = bias[gn], b1 = bias[gn + 1];
                float2 v0 = {acc[mt][nt][0] + b0, acc[mt][nt][1] + b1};
                float2 v1 = {acc[mt][nt][2] + b0, acc[mt][nt][3] + b1};
                *(float2*)&C[(size_t)gm * D_MODEL + gn] = v0;
                *(float2*)&C[(size_t)(gm + 8) * D_MODEL + gn] = v1;
            } else {
                const float b0 = bias[gn], b1 = bias[gn + 1];
                const int sec = gn >> 10, fr = gn & 1023;
                const int hh = fr >> 6, dd = fr & 63;
#pragma unroll
                for (int e2 = 0; e2 < 2; e2++) {
                    const int row = gm + e2 * 8;
                    const int bb = row >> 11, s = row & 2047;
                    float2 w = {acc[mt][nt][e2 * 2 + 0] + b0,
                                acc[mt][nt][e2 * 2 + 1] + b1};
                    if (sec == 0)
                        *(float2*)&g_q[(((size_t)bb * NH + hh) * S_LEN + s) * HD + dd] = w;
                    else
                        *(float2*)&KV[((((size_t)bb * 2 + (sec - 1)) * NH + hh) * S_LEN + s) * HD + dd] = w;
                }
            }
        }
    }
}

// ---------------- flash attention: 128-row Q tile, 256 threads, 8x4 microtile ----------------
// Q[128][64] + P[128][64] + K/V[64][64]; 96 KB smem -> 2 CTAs/SM, 4 warps/SMSP.
// K/V/P XOR chunk-swizzled; Q linear. 6 key tiles per block.
#define ATTN_SMEM_BYTES 98304

__global__ __launch_bounds__(256, 2) void attn_k(const float* __restrict__ KV)
{
    extern __shared__ float sm[];
    float* Qs = sm;                  // [128][64] linear
    float* Ks = sm + 8192;           // [64][64] swizzled
    float* Vs = sm + 12288;          // [64][64] swizzled
    float* Ps = sm + 16384;          // [128][64] swizzled

    const int bid = blockIdx.x;
    const int qt = bid & 15;         // 16 q-tiles of 128
    const int h  = (bid >> 4) & 15;
    const int b  = bid >> 8;
    const int qs = qt * 128;

    const int tid = threadIdx.x;
    const int tx = tid & 15;         // head-dim / key-col group (x4)
    const int ty = tid >> 4;         // 0..15: query-row group (x8)
    const int i0 = ty * 8;
    const int j0 = tx * 4;
    const int sK = tx & 7;
    const float scale = 0.125f;

    const float* Qg = g_q + (((size_t)b * NH + h) * S_LEN) * HD;
    const float* Kg = KV + ((((size_t)b * 2 + 0) * NH + h) * S_LEN) * HD;
    const float* Vg = KV + ((((size_t)b * 2 + 1) * NH + h) * S_LEN) * HD;

    // load Q tile (pre-scaled), linear, 128 rows
    for (int idx = tid; idx < 2048; idx += 256) {
        const int i = idx >> 4, dc = idx & 15;
        float4 v = *(const float4*)&Qg[(size_t)(qs + i) * HD + dc * 4];
        v.x *= scale; v.y *= scale; v.z *= scale; v.w *= scale;
        *(float4*)&Qs[i * 64 + dc * 4] = v;
    }

    float m_run[8], rsum[8], o[8][4];
#pragma unroll
    for (int r = 0; r < 8; r++) {
        m_run[r] = -1e29f;
        rsum[r] = 0.f;
#pragma unroll
        for (int c = 0; c < 4; c++) o[r][c] = 0.f;
    }

    // key window for 128 q-rows: [qs-256, qs+128) -> 6 tiles of 64
    for (int kt = 0; kt < 6; kt++) {
        const int ks = qs - 256 + kt * 64;
        if (ks + 64 <= 0) continue;

        __syncthreads();
        for (int idx = tid; idx < 1024; idx += 256) {
            const int j = idx >> 4, cc = idx & 15;
            const int gj = ks + j;
            const int pc = cc ^ ((j >> 2) & 7);
            if (gj >= 0) {
                *(float4*)&Ks[j * 64 + pc * 4] = *(const float4*)&Kg[(size_t)gj * HD + cc * 4];
                *(float4*)&Vs[j * 64 + pc * 4] = *(const float4*)&Vg[(size_t)gj * HD + cc * 4];
            } else {
                float4 z = make_float4(0.f, 0.f, 0.f, 0.f);
                *(float4*)&Ks[j * 64 + pc * 4] = z;
                *(float4*)&Vs[j * 64 + pc * 4] = z;
            }
        }
        __syncthreads();

        // ---- scores ----
        float s[8][4];
#pragma unroll
        for (int r = 0; r < 8; r++)
#pragma unroll
            for (int c = 0; c < 4; c++) s[r][c] = 0.f;
#pragma unroll 4
        for (int dc = 0; dc < 16; dc++) {
            float4 k4[4];
#pragma unroll
            for (int c = 0; c < 4; c++)
                k4[c] = *(const float4*)&Ks[(j0 + c) * 64 + (dc ^ sK) * 4];
#pragma unroll
            for (int r = 0; r < 8; r++) {
                const float4 q = *(const float4*)&Qs[(i0 + r) * 64 + dc * 4];
#pragma unroll
                for (int c = 0; c < 4; c++)
                    s[r][c] += q.x * k4[c].x + q.y * k4[c].y
                             + q.z * k4[c].z + q.w * k4[c].w;
            }
        }
        // mask
#pragma unroll
        for (int r = 0; r < 8; r++) {
            const int gi = qs + i0 + r;
#pragma unroll
            for (int c = 0; c < 4; c++) {
                const int gj = ks + j0 + c;
                const bool ok = (gj >= 0) && (gj <= gi) && (gj > gi - WINDOW);
                if (!ok) s[r][c] = -1e30f;
            }
        }

        // ---- per-row tile max (all-reduce over 16 tx lanes) ----
        float tmax[8];
#pragma unroll
        for (int r = 0; r < 8; r++) {
            float m = fmaxf(fmaxf(s[r][0], s[r][1]), fmaxf(s[r][2], s[r][3]));
#pragma unroll
            for (int w = 1; w < 16; w <<= 1)
                m = fmaxf(m, __shfl_xor_sync(0xffffffffu, m, w));
            tmax[r] = m;
        }

        // ---- online softmax update; P -> swizzled smem ----
#pragma unroll
        for (int r = 0; r < 8; r++) {
            const float m_new = fmaxf(m_run[r], tmax[r]);
            const float alpha = __expf(m_run[r] - m_new);
            const int sP = ((i0 + r) >> 2) & 7;
            float* prow = Ps + (i0 + r) * 64 + (tx ^ sP) * 4;
            float lsum = 0.f;
#pragma unroll
            for (int c = 0; c < 4; c++) {
                const float p = __expf(s[r][c] - m_new);
                prow[c] = p;
                lsum += p;
            }
#pragma unroll
            for (int w = 1; w < 16; w <<= 1)
                lsum += __shfl_xor_sync(0xffffffffu, lsum, w);
            rsum[r] = rsum[r] * alpha + lsum;
#pragma unroll
            for (int c = 0; c < 4; c++) o[r][c] *= alpha;
            m_run[r] = m_new;
        }
        __syncthreads();

        // ---- PV ----
#pragma unroll 4
        for (int jc = 0; jc < 16; jc++) {
            float4 v4[4];
            const int sv = jc & 7;
#pragma unroll
            for (int jj = 0; jj < 4; jj++)
                v4[jj] = *(const float4*)&Vs[(jc * 4 + jj) * 64 + (tx ^ sv) * 4];
#pragma unroll
            for (int r = 0; r < 8; r++) {
                const int sP = ((i0 + r) >> 2) & 7;
                const float4 p = *(const float4*)&Ps[(i0 + r) * 64 + (jc ^ sP) * 4];
                o[r][0] += p.x * v4[0].x + p.y * v4[1].x + p.z * v4[2].x + p.w * v4[3].x;
                o[r][1] += p.x * v4[0].y + p.y * v4[1].y + p.z * v4[2].y + p.w * v4[3].y;
                o[r][2] += p.x * v4[0].z + p.y * v4[1].z + p.z * v4[2].z + p.w * v4[3].z;
                o[r][3] += p.x * v4[0].w + p.y * v4[1].w + p.z * v4[2].w + p.w * v4[3].w;
            }
        }
    }

    // fused epilogue: normalize, hi/hi/lo split bf16 into g_ahat (8B stores)
#pragma unroll
    for (int r = 0; r < 8; r++) {
        const float ri = 1.f / rsum[r];
        const size_t m = (size_t)b * S_LEN + qs + i0 + r;
        __nv_bfloat16* row = g_ahat + m * KEFF;
        const int k = h * HD + j0;
        float v0 = o[r][0] * ri, v1 = o[r][1] * ri;
        float v2 = o[r][2] * ri, v3 = o[r][3] * ri;
        float h0 = __bfloat162float(__float2bfloat16(v0));
        float h1 = __bfloat162float(__float2bfloat16(v1));
        float h2 = __bfloat162float(__float2bfloat16(v2));
        float h3 = __bfloat162float(__float2bfloat16(v3));
        uint2 H = {bf2pack(v0, v1), bf2pack(v2, v3)};
        uint2 L = {bf2pack(v0 - h0, v1 - h1), bf2pack(v2 - h2, v3 - h3)};
        *(uint2*)&row[k]        = H;
        *(uint2*)&row[1024 + k] = H;
        *(uint2*)&row[2048 + k] = L;
    }
}

// ---------------------------------------------------------------------------
extern "C" void kernel_launch(void* const* d_in, const int* in_sizes, int n_in,
                              void* d_out, int out_size)
{
    const float* x      = (const float*)d_in[0];
    const float* w_attn = (const float*)d_in[1];
    const float* b_attn = (const float*)d_in[2];
    const float* w_proj = (const float*)d_in[3];
    const float* b_proj = (const float*)d_in[4];
    float* out = (float*)d_out;
    float* kv  = out + OUT_ELEMS;

    cudaFuncSetAttribute(attn_k, cudaFuncAttributeMaxDynamicSharedMemorySize, ATTN_SMEM_BYTES);
    cudaFuncSetAttribute(gemm_mma<0>, cudaFuncAttributeMaxDynamicSharedMemorySize, GEMM_SMEM);
    cudaFuncSetAttribute(gemm_mma<1>, cudaFuncAttributeMaxDynamicSharedMemorySize, GEMM_SMEM);

    __nv_bfloat16 *xhat, *ahat, *wat, *wpt;
    cudaGetSymbolAddress((void**)&xhat, g_xhat);
    cudaGetSymbolAddress((void**)&ahat, g_ahat);
    cudaGetSymbolAddress((void**)&wat,  g_wat);
    cudaGetSymbolAddress((void**)&wpt,  g_wpt);

    // 1) split conversions of inputs (vectorized)
    convA_k<<<(TOKENS * 256 + 255) / 256, 256>>>(x, xhat, TOKENS * 256);
    {
        dim3 blk(8, 32);
        convBt_k<<<dim3(3 * D_MODEL / 32, D_MODEL / 32), blk>>>(w_attn, wat, 3 * D_MODEL);
        convBt_k<<<dim3(D_MODEL / 32, D_MODEL / 32),     blk>>>(w_proj, wpt, D_MODEL);
    }

    // 2) QKV projection: Q -> g_q, K/V -> present tail of d_out
    gemm_mma<1><<<dim3(3 * D_MODEL / 128, TOKENS / 128), 256, GEMM_SMEM>>>(
        xhat, wat, b_attn, nullptr, kv);

    // 3) flash sliding-window attention (128-row Q tiles) -> g_ahat
    attn_k<<<BATCH * NH * (S_LEN / 128), 256, ATTN_SMEM_BYTES>>>(kv);

    // 4) output projection -> d_out head
    gemm_mma<0><<<dim3(D_MODEL / 128, TOKENS / 128), 256, GEMM_SMEM>>>(
        ahat, wpt, b_proj, out, nullptr);
}

// round 12
// speedup vs baseline: 1.3785x; 1.3785x over previous
#include <cuda_runtime.h>
#include <cuda_fp16.h>
#include <cstdint>

// Problem constants
#define BATCH   2
#define S_LEN   2048
#define D_MODEL 1024
#define NH      16
#define HD      64
#define WINDOW  256
#define TOKENS  (BATCH * S_LEN)               // 4096
#define OUT_ELEMS ((size_t)TOKENS * D_MODEL)  // 4194304
#define KEFF    2048                          // 2 * 1024 (fp16 [Ah|Al] . [Bh|Bh])
#define NCHUNK  32                            // KEFF / 64

// ---------------- device scratch (allocation-free rule) ----------------
__device__ __align__(128) float g_q [BATCH * NH * S_LEN * HD];
__device__ __align__(128) __half g_xhat[(size_t)TOKENS * KEFF];      // [A_hi|A_lo]
__device__ __align__(128) __half g_ahat[(size_t)TOKENS * KEFF];
__device__ __align__(128) __half g_wat [(size_t)3 * D_MODEL * KEFF]; // W^T [B_hi|B_hi]
__device__ __align__(128) __half g_wpt [(size_t)D_MODEL * KEFF];

// ---------------- helpers ----------------
__device__ __forceinline__ uint32_t smem_u32(const void* p) {
    uint32_t a;
    asm("{ .reg .u64 t; cvta.to.shared.u64 t, %1; cvt.u32.u64 %0, t; }" : "=r"(a) : "l"(p));
    return a;
}
__device__ __forceinline__ void cp16(uint32_t saddr, const void* g) {
    asm volatile("cp.async.cg.shared.global [%0], [%1], 16;" :: "r"(saddr), "l"(g));
}
#define CP_COMMIT() asm volatile("cp.async.commit_group;" ::: "memory")
#define CP_WAIT1()  asm volatile("cp.async.wait_group 1;" ::: "memory")
#define CP_WAIT0()  asm volatile("cp.async.wait_group 0;" ::: "memory")

__device__ __forceinline__ void ldmx4(uint32_t* r, uint32_t addr) {
    asm volatile("ldmatrix.sync.aligned.m8n8.x4.shared.b16 {%0,%1,%2,%3}, [%4];"
                 : "=r"(r[0]), "=r"(r[1]), "=r"(r[2]), "=r"(r[3]) : "r"(addr));
}
__device__ __forceinline__ void mma16816(float* c, const uint32_t* a, const uint32_t* b) {
    asm volatile(
        "mma.sync.aligned.m16n8k16.row.col.f32.f16.f16.f32 "
        "{%0,%1,%2,%3}, {%4,%5,%6,%7}, {%8,%9}, {%0,%1,%2,%3};"
        : "+f"(c[0]), "+f"(c[1]), "+f"(c[2]), "+f"(c[3])
        : "r"(a[0]), "r"(a[1]), "r"(a[2]), "r"(a[3]), "r"(b[0]), "r"(b[1]));
}
// pack two floats into half2 word
__device__ __forceinline__ uint32_t h2pack(float a, float b) {
    __half2 t = __floats2half2_rn(a, b);
    return *reinterpret_cast<uint32_t*>(&t);
}

// ---------------- split conversion kernels (vectorized, fp16 2-term) ----------------
// fp32 [M,1024] -> fp16 [M,2048] segments [hi | lo]; 4 elems/thread
__global__ void convA_k(const float* __restrict__ A, __half* __restrict__ O, int total4)
{
    int idx = blockIdx.x * blockDim.x + threadIdx.x;
    if (idx >= total4) return;
    const int m = idx >> 8;
    const int k = (idx & 255) * 4;
    float4 v = *(const float4*)&A[(size_t)m * 1024 + k];
    float h0 = __half2float(__float2half_rn(v.x));
    float h1 = __half2float(__float2half_rn(v.y));
    float h2 = __half2float(__float2half_rn(v.z));
    float h3 = __half2float(__float2half_rn(v.w));
    uint2 H = {h2pack(v.x, v.y), h2pack(v.z, v.w)};
    uint2 L = {h2pack(v.x - h0, v.y - h1), h2pack(v.z - h2, v.w - h3)};
    __half* row = O + (size_t)m * KEFF;
    *(uint2*)&row[k]        = H;
    *(uint2*)&row[1024 + k] = L;
}
// W fp32 [1024, N] row-major -> Bt fp16 [N, 2048] segments [hi | hi] (transpose)
__global__ void convBt_k(const float* __restrict__ W, __half* __restrict__ O, int N)
{
    __shared__ float tile[32][33];
    const int k0 = blockIdx.y * 32, n0 = blockIdx.x * 32;
    const int tx = threadIdx.x;   // 0..7
    const int ty = threadIdx.y;   // 0..31
    float4 w4 = *(const float4*)&W[(size_t)(k0 + ty) * N + n0 + tx * 4];
    tile[ty][tx * 4 + 0] = w4.x;
    tile[ty][tx * 4 + 1] = w4.y;
    tile[ty][tx * 4 + 2] = w4.z;
    tile[ty][tx * 4 + 3] = w4.w;
    __syncthreads();
    const int tid = ty * 8 + tx;
    const int nr = tid >> 3;
    const int kq = tid & 7;
    float v0 = tile[kq * 4 + 0][nr];
    float v1 = tile[kq * 4 + 1][nr];
    float v2 = tile[kq * 4 + 2][nr];
    float v3 = tile[kq * 4 + 3][nr];
    uint2 H = {h2pack(v0, v1), h2pack(v2, v3)};
    __half* row = O + (size_t)(n0 + nr) * KEFF;
    const int k = k0 + kq * 4;
    *(uint2*)&row[k]        = H;
    *(uint2*)&row[1024 + k] = H;
}

// ---------------- mma.sync GEMM (structure = R10 winner, fp16, K_eff 2048) ----------------
#define TILE_BYTES  18432
#define BUF_BYTES   36864
#define GEMM_SMEM   110592

template<int MODE>
__global__ __launch_bounds__(256, 2) void gemm_mma(const __half* __restrict__ A,
                                                   const __half* __restrict__ Bt,
                                                   const float* __restrict__ bias,
                                                   float* __restrict__ C,
                                                   float* __restrict__ KV)
{
    extern __shared__ char smem[];
    const uint32_t sb = smem_u32(smem);
    const int tid = threadIdx.x;
    const int wid = tid >> 5, lid = tid & 31;
    const int m0 = blockIdx.y * 128, n0 = blockIdx.x * 128;
    const int mbase = (wid & 1) * 64;
    const int nbase = (wid >> 1) * 32;

    const char* Abase = (const char*)(A  + (size_t)m0 * KEFF);
    const char* Bbase = (const char*)(Bt + (size_t)n0 * KEFF);

    const uint32_t a_row_off = (uint32_t)((mbase + ((lid >> 3) & 1) * 8 + (lid & 7)) * 144
                                          + ((lid >> 4) * 8) * 2);
    const uint32_t b_row_off = (uint32_t)((nbase + ((lid >> 4) & 1) * 8 + (lid & 7)) * 144
                                          + (((lid >> 3) & 1) * 8) * 2);

    float acc[4][4][4];
#pragma unroll
    for (int mt = 0; mt < 4; mt++)
#pragma unroll
        for (int nt = 0; nt < 4; nt++)
#pragma unroll
            for (int i = 0; i < 4; i++) acc[mt][nt][i] = 0.f;

#define PREFETCH(c, buf)                                                          \
    {                                                                             \
        const size_t kbyte = (size_t)(c) * 128;                                   \
        const uint32_t abuf = sb + (buf) * BUF_BYTES;                             \
        const uint32_t bbuf = abuf + TILE_BYTES;                                  \
        _Pragma("unroll")                                                         \
        for (int i = 0; i < 4; i++) {                                             \
            int idx = tid + i * 256;                                              \
            int row = idx >> 3, seg = idx & 7;                                    \
            uint32_t so = row * 144 + seg * 16;                                   \
            cp16(abuf + so, Abase + (size_t)row * (KEFF * 2) + kbyte + seg * 16); \
            cp16(bbuf + so, Bbase + (size_t)row * (KEFF * 2) + kbyte + seg * 16); \
        }                                                                         \
    }

    PREFETCH(0, 0); CP_COMMIT();
    PREFETCH(1, 1); CP_COMMIT();

    int buf = 0;
    for (int c = 0; c < NCHUNK; c++) {
        if (c == NCHUNK - 1) { CP_WAIT0(); } else { CP_WAIT1(); }
        __syncthreads();
        if (c + 2 < NCHUNK) {
            int nbuf = buf + 2; if (nbuf >= 3) nbuf -= 3;
            PREFETCH(c + 2, nbuf);
            CP_COMMIT();
        }
        const uint32_t abuf = sb + buf * BUF_BYTES;
        const uint32_t bbuf = abuf + TILE_BYTES;
#pragma unroll
        for (int ks = 0; ks < 4; ks++) {
            const uint32_t kb = (uint32_t)ks * 32;
            uint32_t ar[4][4];
            uint32_t br[4][2];
#pragma unroll
            for (int mt = 0; mt < 4; mt++)
                ldmx4(ar[mt], abuf + a_row_off + mt * (16 * 144) + kb);
#pragma unroll
            for (int p = 0; p < 2; p++) {
                uint32_t r[4];
                ldmx4(r, bbuf + b_row_off + p * (16 * 144) + kb);
                br[p * 2][0] = r[0]; br[p * 2][1] = r[1];
                br[p * 2 + 1][0] = r[2]; br[p * 2 + 1][1] = r[3];
            }
#pragma unroll
            for (int mt = 0; mt < 4; mt++)
#pragma unroll
                for (int nt = 0; nt < 4; nt++)
                    mma16816(acc[mt][nt], ar[mt], br[nt]);
        }
        if (++buf == 3) buf = 0;
    }
#undef PREFETCH

    const int lrow = lid >> 2;
    const int lcol = (lid & 3) * 2;
#pragma unroll
    for (int mt = 0; mt < 4; mt++) {
        const int gm = m0 + mbase + mt * 16 + lrow;
#pragma unroll
        for (int nt = 0; nt < 4; nt++) {
            const int gn = n0 + nbase + nt * 8 + lcol;
            if (MODE == 0) {
                const float b0 = bias[gn], b1 = bias[gn + 1];
                float2 v0 = {acc[mt][nt][0] + b0, acc[mt][nt][1] + b1};
                float2 v1 = {acc[mt][nt][2] + b0, acc[mt][nt][3] + b1};
                *(float2*)&C[(size_t)gm * D_MODEL + gn] = v0;
                *(float2*)&C[(size_t)(gm + 8) * D_MODEL + gn] = v1;
            } else {
                const float b0 = bias[gn], b1 = bias[gn + 1];
                const int sec = gn >> 10, fr = gn & 1023;
                const int hh = fr >> 6, dd = fr & 63;
#pragma unroll
                for (int e2 = 0; e2 < 2; e2++) {
                    const int row = gm + e2 * 8;
                    const int bb = row >> 11, s = row & 2047;
                    float2 w = {acc[mt][nt][e2 * 2 + 0] + b0,
                                acc[mt][nt][e2 * 2 + 1] + b1};
                    if (sec == 0)
                        *(float2*)&g_q[(((size_t)bb * NH + hh) * S_LEN + s) * HD + dd] = w;
                    else
                        *(float2*)&KV[((((size_t)bb * 2 + (sec - 1)) * NH + hh) * S_LEN + s) * HD + dd] = w;
                }
            }
        }
    }
}

// ---------------- flash attention (R10 winner: 128 threads, 8x4 microtile) ----------------
// K/V/P tiles 64x64 f32 with XOR chunk swizzle; Q linear. 64 KB smem -> 3 CTAs/SM.
#define ATTN_SMEM_BYTES 65536

__global__ __launch_bounds__(128, 3) void attn_k(const float* __restrict__ KV)
{
    extern __shared__ float sm[];
    float* Qs = sm;                 // [64][64] linear
    float* Ks = sm + 4096;          // swizzled
    float* Vs = sm + 8192;          // swizzled
    float* Ps = sm + 12288;         // swizzled

    const int bid = blockIdx.x;
    const int qt = bid & 31;
    const int h  = (bid >> 5) & 15;
    const int b  = bid >> 9;
    const int qs = qt * 64;

    const int tid = threadIdx.x;
    const int tx = tid & 15;
    const int ty = tid >> 4;        // 0..7
    const int i0 = ty * 8;
    const int j0 = tx * 4;
    const int sK = tx & 7;
    const float scale = 0.125f;

    const float* Qg = g_q + (((size_t)b * NH + h) * S_LEN) * HD;
    const float* Kg = KV + ((((size_t)b * 2 + 0) * NH + h) * S_LEN) * HD;
    const float* Vg = KV + ((((size_t)b * 2 + 1) * NH + h) * S_LEN) * HD;

    for (int idx = tid; idx < 1024; idx += 128) {
        const int i = idx >> 4, dc = idx & 15;
        float4 v = *(const float4*)&Qg[(size_t)(qs + i) * HD + dc * 4];
        v.x *= scale; v.y *= scale; v.z *= scale; v.w *= scale;
        *(float4*)&Qs[i * 64 + dc * 4] = v;
    }

    float m_run[8], rsum[8], o[8][4];
#pragma unroll
    for (int r = 0; r < 8; r++) {
        m_run[r] = -1e29f;
        rsum[r] = 0.f;
#pragma unroll
        for (int c = 0; c < 4; c++) o[r][c] = 0.f;
    }

    for (int kt = 0; kt < 5; kt++) {
        const int ks = qs - 256 + kt * 64;
        if (ks + 64 <= 0) continue;

        __syncthreads();
        for (int idx = tid; idx < 1024; idx += 128) {
            const int j = idx >> 4, cc = idx & 15;
            const int gj = ks + j;
            const int pc = cc ^ ((j >> 2) & 7);
            if (gj >= 0) {
                *(float4*)&Ks[j * 64 + pc * 4] = *(const float4*)&Kg[(size_t)gj * HD + cc * 4];
                *(float4*)&Vs[j * 64 + pc * 4] = *(const float4*)&Vg[(size_t)gj * HD + cc * 4];
            } else {
                float4 z = make_float4(0.f, 0.f, 0.f, 0.f);
                *(float4*)&Ks[j * 64 + pc * 4] = z;
                *(float4*)&Vs[j * 64 + pc * 4] = z;
            }
        }
        __syncthreads();

        float s[8][4];
#pragma unroll
        for (int r = 0; r < 8; r++)
#pragma unroll
            for (int c = 0; c < 4; c++) s[r][c] = 0.f;
#pragma unroll 4
        for (int dc = 0; dc < 16; dc++) {
            float4 k4[4];
#pragma unroll
            for (int c = 0; c < 4; c++)
                k4[c] = *(const float4*)&Ks[(j0 + c) * 64 + (dc ^ sK) * 4];
#pragma unroll
            for (int r = 0; r < 8; r++) {
                const float4 q = *(const float4*)&Qs[(i0 + r) * 64 + dc * 4];
#pragma unroll
                for (int c = 0; c < 4; c++)
                    s[r][c] += q.x * k4[c].x + q.y * k4[c].y
                             + q.z * k4[c].z + q.w * k4[c].w;
            }
        }
#pragma unroll
        for (int r = 0; r < 8; r++) {
            const int gi = qs + i0 + r;
#pragma unroll
            for (int c = 0; c < 4; c++) {
                const int gj = ks + j0 + c;
                const bool ok = (gj >= 0) && (gj <= gi) && (gj > gi - WINDOW);
                if (!ok) s[r][c] = -1e30f;
            }
        }

        float tmax[8];
#pragma unroll
        for (int r = 0; r < 8; r++) {
            float m = fmaxf(fmaxf(s[r][0], s[r][1]), fmaxf(s[r][2], s[r][3]));
#pragma unroll
            for (int w = 1; w < 16; w <<= 1)
                m = fmaxf(m, __shfl_xor_sync(0xffffffffu, m, w));
            tmax[r] = m;
        }

#pragma unroll
        for (int r = 0; r < 8; r++) {
            const float m_new = fmaxf(m_run[r], tmax[r]);
            const float alpha = __expf(m_run[r] - m_new);
            const int sP = ((i0 + r) >> 2) & 7;
            float* prow = Ps + (i0 + r) * 64 + (tx ^ sP) * 4;
            float lsum = 0.f;
#pragma unroll
            for (int c = 0; c < 4; c++) {
                const float p = __expf(s[r][c] - m_new);
                prow[c] = p;
                lsum += p;
            }
#pragma unroll
            for (int w = 1; w < 16; w <<= 1)
                lsum += __shfl_xor_sync(0xffffffffu, lsum, w);
            rsum[r] = rsum[r] * alpha + lsum;
#pragma unroll
            for (int c = 0; c < 4; c++) o[r][c] *= alpha;
            m_run[r] = m_new;
        }
        __syncthreads();

#pragma unroll 4
        for (int jc = 0; jc < 16; jc++) {
            float4 v4[4];
            const int sv = jc & 7;
#pragma unroll
            for (int jj = 0; jj < 4; jj++)
                v4[jj] = *(const float4*)&Vs[(jc * 4 + jj) * 64 + (tx ^ sv) * 4];
#pragma unroll
            for (int r = 0; r < 8; r++) {
                const int sP = ((i0 + r) >> 2) & 7;
                const float4 p = *(const float4*)&Ps[(i0 + r) * 64 + (jc ^ sP) * 4];
                o[r][0] += p.x * v4[0].x + p.y * v4[1].x + p.z * v4[2].x + p.w * v4[3].x;
                o[r][1] += p.x * v4[0].y + p.y * v4[1].y + p.z * v4[2].y + p.w * v4[3].y;
                o[r][2] += p.x * v4[0].z + p.y * v4[1].z + p.z * v4[2].z + p.w * v4[3].z;
                o[r][3] += p.x * v4[0].w + p.y * v4[1].w + p.z * v4[2].w + p.w * v4[3].w;
            }
        }
    }

    // fused epilogue: normalize, [hi|lo] fp16 split into g_ahat (8B stores)
#pragma unroll
    for (int r = 0; r < 8; r++) {
        const float ri = 1.f / rsum[r];
        const size_t m = (size_t)b * S_LEN + qs + i0 + r;
        __half* row = g_ahat + m * KEFF;
        const int k = h * HD + j0;
        float v0 = o[r][0] * ri, v1 = o[r][1] * ri;
        float v2 = o[r][2] * ri, v3 = o[r][3] * ri;
        float h0 = __half2float(__float2half_rn(v0));
        float h1 = __half2float(__float2half_rn(v1));
        float h2 = __half2float(__float2half_rn(v2));
        float h3 = __half2float(__float2half_rn(v3));
        uint2 H = {h2pack(v0, v1), h2pack(v2, v3)};
        uint2 L = {h2pack(v0 - h0, v1 - h1), h2pack(v2 - h2, v3 - h3)};
        *(uint2*)&row[k]        = H;
        *(uint2*)&row[1024 + k] = L;
    }
}

// ---------------------------------------------------------------------------
extern "C" void kernel_launch(void* const* d_in, const int* in_sizes, int n_in,
                              void* d_out, int out_size)
{
    const float* x      = (const float*)d_in[0];
    const float* w_attn = (const float*)d_in[1];
    const float* b_attn = (const float*)d_in[2];
    const float* w_proj = (const float*)d_in[3];
    const float* b_proj = (const float*)d_in[4];
    float* out = (float*)d_out;
    float* kv  = out + OUT_ELEMS;

    cudaFuncSetAttribute(attn_k, cudaFuncAttributeMaxDynamicSharedMemorySize, ATTN_SMEM_BYTES);
    cudaFuncSetAttribute(gemm_mma<0>, cudaFuncAttributeMaxDynamicSharedMemorySize, GEMM_SMEM);
    cudaFuncSetAttribute(gemm_mma<1>, cudaFuncAttributeMaxDynamicSharedMemorySize, GEMM_SMEM);

    __half *xhat, *ahat, *wat, *wpt;
    cudaGetSymbolAddress((void**)&xhat, g_xhat);
    cudaGetSymbolAddress((void**)&ahat, g_ahat);
    cudaGetSymbolAddress((void**)&wat,  g_wat);
    cudaGetSymbolAddress((void**)&wpt,  g_wpt);

    // 1) split conversions of inputs (fp16 2-term)
    convA_k<<<(TOKENS * 256 + 255) / 256, 256>>>(x, xhat, TOKENS * 256);
    {
        dim3 blk(8, 32);
        convBt_k<<<dim3(3 * D_MODEL / 32, D_MODEL / 32), blk>>>(w_attn, wat, 3 * D_MODEL);
        convBt_k<<<dim3(D_MODEL / 32, D_MODEL / 32),     blk>>>(w_proj, wpt, D_MODEL);
    }

    // 2) QKV projection: Q -> g_q, K/V -> present tail of d_out
    gemm_mma<1><<<dim3(3 * D_MODEL / 128, TOKENS / 128), 256, GEMM_SMEM>>>(
        xhat, wat, b_attn, nullptr, kv);

    // 3) flash sliding-window attention -> g_ahat (fp16 2-term split)
    attn_k<<<BATCH * NH * (S_LEN / 64), 128, ATTN_SMEM_BYTES>>>(kv);

    // 4) output projection -> d_out head
    gemm_mma<0><<<dim3(D_MODEL / 128, TOKENS / 128), 256, GEMM_SMEM>>>(
        ahat, wpt, b_proj, out, nullptr);
}

// round 13
// speedup vs baseline: 2.0249x; 1.4689x over previous
#include <cuda_runtime.h>
#include <cuda_fp16.h>
#include <cstdint>

// Problem constants
#define BATCH   2
#define S_LEN   2048
#define D_MODEL 1024
#define NH      16
#define HD      64
#define WINDOW  256
#define TOKENS  (BATCH * S_LEN)               // 4096
#define OUT_ELEMS ((size_t)TOKENS * D_MODEL)  // 4194304
#define KEFF    2048                          // 2 * 1024 (fp16 [Ah|Al] . [Bh|Bh])
#define NCHUNK  32                            // KEFF / 64

// ---------------- device scratch (allocation-free rule) ----------------
__device__ __align__(128) __half g_qh [BATCH * NH * S_LEN * HD];     // fp16 Q (pre-scaled)
__device__ __align__(128) __half g_kh [BATCH * NH * S_LEN * HD];     // fp16 K
__device__ __align__(128) __half g_vh [BATCH * NH * S_LEN * HD];     // fp16 V
__device__ __align__(128) __half g_xhat[(size_t)TOKENS * KEFF];      // [A_hi|A_lo]
__device__ __align__(128) __half g_ahat[(size_t)TOKENS * KEFF];
__device__ __align__(128) __half g_wat [(size_t)3 * D_MODEL * KEFF]; // W^T [B_hi|B_hi]
__device__ __align__(128) __half g_wpt [(size_t)D_MODEL * KEFF];

// ---------------- helpers ----------------
__device__ __forceinline__ uint32_t smem_u32(const void* p) {
    uint32_t a;
    asm("{ .reg .u64 t; cvta.to.shared.u64 t, %1; cvt.u32.u64 %0, t; }" : "=r"(a) : "l"(p));
    return a;
}
__device__ __forceinline__ void cp16(uint32_t saddr, const void* g) {
    asm volatile("cp.async.cg.shared.global [%0], [%1], 16;" :: "r"(saddr), "l"(g));
}
#define CP_COMMIT() asm volatile("cp.async.commit_group;" ::: "memory")
#define CP_WAIT1()  asm volatile("cp.async.wait_group 1;" ::: "memory")
#define CP_WAIT0()  asm volatile("cp.async.wait_group 0;" ::: "memory")

__device__ __forceinline__ void ldmx4(uint32_t* r, uint32_t addr) {
    asm volatile("ldmatrix.sync.aligned.m8n8.x4.shared.b16 {%0,%1,%2,%3}, [%4];"
                 : "=r"(r[0]), "=r"(r[1]), "=r"(r[2]), "=r"(r[3]) : "r"(addr));
}
__device__ __forceinline__ void ldmx4t(uint32_t* r, uint32_t addr) {
    asm volatile("ldmatrix.sync.aligned.m8n8.x4.trans.shared.b16 {%0,%1,%2,%3}, [%4];"
                 : "=r"(r[0]), "=r"(r[1]), "=r"(r[2]), "=r"(r[3]) : "r"(addr));
}
__device__ __forceinline__ void mma16816(float* c, const uint32_t* a, const uint32_t* b) {
    asm volatile(
        "mma.sync.aligned.m16n8k16.row.col.f32.f16.f16.f32 "
        "{%0,%1,%2,%3}, {%4,%5,%6,%7}, {%8,%9}, {%0,%1,%2,%3};"
        : "+f"(c[0]), "+f"(c[1]), "+f"(c[2]), "+f"(c[3])
        : "r"(a[0]), "r"(a[1]), "r"(a[2]), "r"(a[3]), "r"(b[0]), "r"(b[1]));
}
__device__ __forceinline__ uint32_t h2pack(float a, float b) {
    __half2 t = __floats2half2_rn(a, b);
    return *reinterpret_cast<uint32_t*>(&t);
}

// ---------------- split conversion kernels (fp16 2-term) ----------------
__global__ void convA_k(const float* __restrict__ A, __half* __restrict__ O, int total4)
{
    int idx = blockIdx.x * blockDim.x + threadIdx.x;
    if (idx >= total4) return;
    const int m = idx >> 8;
    const int k = (idx & 255) * 4;
    float4 v = *(const float4*)&A[(size_t)m * 1024 + k];
    float h0 = __half2float(__float2half_rn(v.x));
    float h1 = __half2float(__float2half_rn(v.y));
    float h2 = __half2float(__float2half_rn(v.z));
    float h3 = __half2float(__float2half_rn(v.w));
    uint2 H = {h2pack(v.x, v.y), h2pack(v.z, v.w)};
    uint2 L = {h2pack(v.x - h0, v.y - h1), h2pack(v.z - h2, v.w - h3)};
    __half* row = O + (size_t)m * KEFF;
    *(uint2*)&row[k]        = H;
    *(uint2*)&row[1024 + k] = L;
}
__global__ void convBt_k(const float* __restrict__ W, __half* __restrict__ O, int N)
{
    __shared__ float tile[32][33];
    const int k0 = blockIdx.y * 32, n0 = blockIdx.x * 32;
    const int tx = threadIdx.x;   // 0..7
    const int ty = threadIdx.y;   // 0..31
    float4 w4 = *(const float4*)&W[(size_t)(k0 + ty) * N + n0 + tx * 4];
    tile[ty][tx * 4 + 0] = w4.x;
    tile[ty][tx * 4 + 1] = w4.y;
    tile[ty][tx * 4 + 2] = w4.z;
    tile[ty][tx * 4 + 3] = w4.w;
    __syncthreads();
    const int tid = ty * 8 + tx;
    const int nr = tid >> 3;
    const int kq = tid & 7;
    float v0 = tile[kq * 4 + 0][nr];
    float v1 = tile[kq * 4 + 1][nr];
    float v2 = tile[kq * 4 + 2][nr];
    float v3 = tile[kq * 4 + 3][nr];
    uint2 H = {h2pack(v0, v1), h2pack(v2, v3)};
    __half* row = O + (size_t)(n0 + nr) * KEFF;
    const int k = k0 + kq * 4;
    *(uint2*)&row[k]        = H;
    *(uint2*)&row[1024 + k] = H;
}

// ---------------- mma.sync GEMM (R12 structure; MODE-1 also emits fp16 Q/K/V) ----------------
#define TILE_BYTES  18432
#define BUF_BYTES   36864
#define GEMM_SMEM   110592

template<int MODE>
__global__ __launch_bounds__(256, 2) void gemm_mma(const __half* __restrict__ A,
                                                   const __half* __restrict__ Bt,
                                                   const float* __restrict__ bias,
                                                   float* __restrict__ C,
                                                   float* __restrict__ KV)
{
    extern __shared__ char smem[];
    const uint32_t sb = smem_u32(smem);
    const int tid = threadIdx.x;
    const int wid = tid >> 5, lid = tid & 31;
    const int m0 = blockIdx.y * 128, n0 = blockIdx.x * 128;
    const int mbase = (wid & 1) * 64;
    const int nbase = (wid >> 1) * 32;

    const char* Abase = (const char*)(A  + (size_t)m0 * KEFF);
    const char* Bbase = (const char*)(Bt + (size_t)n0 * KEFF);

    const uint32_t a_row_off = (uint32_t)((mbase + ((lid >> 3) & 1) * 8 + (lid & 7)) * 144
                                          + ((lid >> 4) * 8) * 2);
    const uint32_t b_row_off = (uint32_t)((nbase + ((lid >> 4) & 1) * 8 + (lid & 7)) * 144
                                          + (((lid >> 3) & 1) * 8) * 2);

    float acc[4][4][4];
#pragma unroll
    for (int mt = 0; mt < 4; mt++)
#pragma unroll
        for (int nt = 0; nt < 4; nt++)
#pragma unroll
            for (int i = 0; i < 4; i++) acc[mt][nt][i] = 0.f;

#define PREFETCH(c, buf)                                                          \
    {                                                                             \
        const size_t kbyte = (size_t)(c) * 128;                                   \
        const uint32_t abuf = sb + (buf) * BUF_BYTES;                             \
        const uint32_t bbuf = abuf + TILE_BYTES;                                  \
        _Pragma("unroll")                                                         \
        for (int i = 0; i < 4; i++) {                                             \
            int idx = tid + i * 256;                                              \
            int row = idx >> 3, seg = idx & 7;                                    \
            uint32_t so = row * 144 + seg * 16;                                   \
            cp16(abuf + so, Abase + (size_t)row * (KEFF * 2) + kbyte + seg * 16); \
            cp16(bbuf + so, Bbase + (size_t)row * (KEFF * 2) + kbyte + seg * 16); \
        }                                                                         \
    }

    PREFETCH(0, 0); CP_COMMIT();
    PREFETCH(1, 1); CP_COMMIT();

    int buf = 0;
    for (int c = 0; c < NCHUNK; c++) {
        if (c == NCHUNK - 1) { CP_WAIT0(); } else { CP_WAIT1(); }
        __syncthreads();
        if (c + 2 < NCHUNK) {
            int nbuf = buf + 2; if (nbuf >= 3) nbuf -= 3;
            PREFETCH(c + 2, nbuf);
            CP_COMMIT();
        }
        const uint32_t abuf = sb + buf * BUF_BYTES;
        const uint32_t bbuf = abuf + TILE_BYTES;
#pragma unroll
        for (int ks = 0; ks < 4; ks++) {
            const uint32_t kb = (uint32_t)ks * 32;
            uint32_t ar[4][4];
            uint32_t br[4][2];
#pragma unroll
            for (int mt = 0; mt < 4; mt++)
                ldmx4(ar[mt], abuf + a_row_off + mt * (16 * 144) + kb);
#pragma unroll
            for (int p = 0; p < 2; p++) {
                uint32_t r[4];
                ldmx4(r, bbuf + b_row_off + p * (16 * 144) + kb);
                br[p * 2][0] = r[0]; br[p * 2][1] = r[1];
                br[p * 2 + 1][0] = r[2]; br[p * 2 + 1][1] = r[3];
            }
#pragma unroll
            for (int mt = 0; mt < 4; mt++)
#pragma unroll
                for (int nt = 0; nt < 4; nt++)
                    mma16816(acc[mt][nt], ar[mt], br[nt]);
        }
        if (++buf == 3) buf = 0;
    }
#undef PREFETCH

    const int lrow = lid >> 2;
    const int lcol = (lid & 3) * 2;
#pragma unroll
    for (int mt = 0; mt < 4; mt++) {
        const int gm = m0 + mbase + mt * 16 + lrow;
#pragma unroll
        for (int nt = 0; nt < 4; nt++) {
            const int gn = n0 + nbase + nt * 8 + lcol;
            if (MODE == 0) {
                const float b0 = bias[gn], b1 = bias[gn + 1];
                float2 v0 = {acc[mt][nt][0] + b0, acc[mt][nt][1] + b1};
                float2 v1 = {acc[mt][nt][2] + b0, acc[mt][nt][3] + b1};
                *(float2*)&C[(size_t)gm * D_MODEL + gn] = v0;
                *(float2*)&C[(size_t)(gm + 8) * D_MODEL + gn] = v1;
            } else {
                const float b0 = bias[gn], b1 = bias[gn + 1];
                const int sec = gn >> 10, fr = gn & 1023;
                const int hh = fr >> 6, dd = fr & 63;
#pragma unroll
                for (int e2 = 0; e2 < 2; e2++) {
                    const int row = gm + e2 * 8;
                    const int bb = row >> 11, s = row & 2047;
                    float2 w = {acc[mt][nt][e2 * 2 + 0] + b0,
                                acc[mt][nt][e2 * 2 + 1] + b1};
                    const size_t base = (((size_t)bb * NH + hh) * S_LEN + s) * HD + dd;
                    if (sec == 0) {
                        *(uint32_t*)&g_qh[base] = h2pack(w.x * 0.125f, w.y * 0.125f);
                    } else {
                        const size_t kvb =
                            ((((size_t)bb * 2 + (sec - 1)) * NH + hh) * S_LEN + s) * HD + dd;
                        *(float2*)&KV[kvb] = w;    // fp32 `present`
                        if (sec == 1) *(uint32_t*)&g_kh[base] = h2pack(w.x, w.y);
                        else          *(uint32_t*)&g_vh[base] = h2pack(w.x, w.y);
                    }
                }
            }
        }
    }
}

// ---------------- tensor-core flash attention (FA2-style) ----------------
// 128 threads = 4 warps x m16 q-rows. Scores & output in mma accumulators;
// P converted reg->reg into a-fragments; V^T b-frags via ldmatrix.trans.
// Smem: Q/K/V fp16 tiles @144B pitch = 27648 B -> 4 CTAs/SM.
#define ATTN_SMEM_BYTES (3 * 64 * 144)

__global__ __launch_bounds__(128, 4) void attn_k()
{
    extern __shared__ char smem[];
    const uint32_t sb = smem_u32(smem);
    const uint32_t sQ = sb, sK = sb + 9216, sV = sb + 18432;

    const int bid = blockIdx.x;
    const int qt = bid & 31;
    const int h  = (bid >> 5) & 15;
    const int b  = bid >> 9;
    const int qs = qt * 64;

    const int tid = threadIdx.x;
    const int wid = tid >> 5, lid = tid & 31;
    const int mbase = wid * 16;

    const __half* Qg = g_qh + ((size_t)(b * NH + h) * S_LEN + qs) * HD;
    const __half* Kg = g_kh + ((size_t)(b * NH + h) * S_LEN) * HD;
    const __half* Vg = g_vh + ((size_t)(b * NH + h) * S_LEN) * HD;

    // Q tile: 64 rows x 128B
    for (int idx = tid; idx < 512; idx += 128) {
        const int row = idx >> 3, seg = idx & 7;
        cp16(sQ + row * 144 + seg * 16, (const char*)Qg + row * 128 + seg * 16);
    }
    CP_COMMIT();

    // fragment address bases (same mapping as the proven GEMM)
    const uint32_t a_off = (uint32_t)((mbase + ((lid >> 3) & 1) * 8 + (lid & 7)) * 144
                                      + ((lid >> 4) * 8) * 2);
    const uint32_t bK_off = (uint32_t)(((((lid >> 4) & 1) * 8) + (lid & 7)) * 144
                                       + (((lid >> 3) & 1) * 8) * 2);
    const int vmid = lid >> 3;
    const uint32_t bV_off = (uint32_t)((((vmid & 1) * 8 + (lid & 7)) * 144)
                                       + ((vmid >> 1) * 8) * 2);

    const int r0 = lid >> 2;          // row within m16 (and +8)
    const int qcol = (lid & 3) * 2;   // col pair within n8

    float o[8][4];
#pragma unroll
    for (int t = 0; t < 8; t++)
#pragma unroll
        for (int i = 0; i < 4; i++) o[t][i] = 0.f;
    float m0r = -1e29f, m1r = -1e29f, rs0 = 0.f, rs1 = 0.f;

    for (int kt = 0; kt < 5; kt++) {
        const int ks = qs - 256 + kt * 64;
        if (ks + 64 <= 0) continue;

        __syncthreads();   // prev tile consumed
        for (int idx = tid; idx < 512; idx += 128) {
            const int row = idx >> 3, seg = idx & 7;
            const int gj = ks + row;
            if (gj >= 0) {
                cp16(sK + row * 144 + seg * 16, (const char*)Kg + (size_t)gj * 128 + seg * 16);
                cp16(sV + row * 144 + seg * 16, (const char*)Vg + (size_t)gj * 128 + seg * 16);
            } else {
                uint4 z = {0u, 0u, 0u, 0u};
                *(uint4*)(smem + 9216  + row * 144 + seg * 16) = z;
                *(uint4*)(smem + 18432 + row * 144 + seg * 16) = z;
            }
        }
        CP_COMMIT();
        CP_WAIT0();
        __syncthreads();

        // ---- scores: C = Q . K^T (8 n-tiles x 4 k-steps) ----
        float c[8][4];
#pragma unroll
        for (int t = 0; t < 8; t++)
#pragma unroll
            for (int i = 0; i < 4; i++) c[t][i] = 0.f;
#pragma unroll
        for (int ks4 = 0; ks4 < 4; ks4++) {
            const uint32_t kb = (uint32_t)ks4 * 32;
            uint32_t aq[4];
            ldmx4(aq, sQ + a_off + kb);
            uint32_t bk[8][2];
#pragma unroll
            for (int p = 0; p < 4; p++) {
                uint32_t r[4];
                ldmx4(r, sK + bK_off + p * (16 * 144) + kb);
                bk[p * 2][0] = r[0]; bk[p * 2][1] = r[1];
                bk[p * 2 + 1][0] = r[2]; bk[p * 2 + 1][1] = r[3];
            }
#pragma unroll
            for (int t = 0; t < 8; t++)
                mma16816(c[t], aq, bk[t]);
        }

        // ---- mask ----
        const int gi0 = qs + mbase + r0, gi1 = gi0 + 8;
#pragma unroll
        for (int t = 0; t < 8; t++) {
            const int cb = ks + t * 8 + qcol;
#pragma unroll
            for (int e = 0; e < 2; e++) {
                const int gj = cb + e;
                if (!(gj >= 0 && gj <= gi0 && gj > gi0 - WINDOW)) c[t][e]     = -1e30f;
                if (!(gj >= 0 && gj <= gi1 && gj > gi1 - WINDOW)) c[t][e + 2] = -1e30f;
            }
        }

        // ---- online softmax (rows r0, r0+8; reduce over lane quad) ----
        float mx0 = -1e30f, mx1 = -1e30f;
#pragma unroll
        for (int t = 0; t < 8; t++) {
            mx0 = fmaxf(mx0, fmaxf(c[t][0], c[t][1]));
            mx1 = fmaxf(mx1, fmaxf(c[t][2], c[t][3]));
        }
#pragma unroll
        for (int w = 1; w < 4; w <<= 1) {
            mx0 = fmaxf(mx0, __shfl_xor_sync(0xffffffffu, mx0, w));
            mx1 = fmaxf(mx1, __shfl_xor_sync(0xffffffffu, mx1, w));
        }
        const float mn0 = fmaxf(m0r, mx0), mn1 = fmaxf(m1r, mx1);
        const float al0 = __expf(m0r - mn0), al1 = __expf(m1r - mn1);

        uint32_t pa[4][4];
        float ls0 = 0.f, ls1 = 0.f;
#pragma unroll
        for (int t = 0; t < 8; t++) {
            const float p0 = __expf(c[t][0] - mn0);
            const float p1 = __expf(c[t][1] - mn0);
            const float p2 = __expf(c[t][2] - mn1);
            const float p3 = __expf(c[t][3] - mn1);
            ls0 += p0 + p1; ls1 += p2 + p3;
            pa[t >> 1][(t & 1) * 2 + 0] = h2pack(p0, p1);
            pa[t >> 1][(t & 1) * 2 + 1] = h2pack(p2, p3);
        }
#pragma unroll
        for (int w = 1; w < 4; w <<= 1) {
            ls0 += __shfl_xor_sync(0xffffffffu, ls0, w);
            ls1 += __shfl_xor_sync(0xffffffffu, ls1, w);
        }
        rs0 = rs0 * al0 + ls0;
        rs1 = rs1 * al1 + ls1;
        m0r = mn0; m1r = mn1;
#pragma unroll
        for (int t = 0; t < 8; t++) {
            o[t][0] *= al0; o[t][1] *= al0;
            o[t][2] *= al1; o[t][3] *= al1;
        }

        // ---- PV: O += P . V (b-frags = V^T via ldmatrix.trans) ----
#pragma unroll
        for (int kk = 0; kk < 4; kk++) {
            uint32_t bv[8][2];
#pragma unroll
            for (int p = 0; p < 4; p++) {
                uint32_t r[4];
                ldmx4t(r, sV + bV_off + kk * (16 * 144) + p * 32);
                bv[p * 2][0] = r[0]; bv[p * 2][1] = r[1];
                bv[p * 2 + 1][0] = r[2]; bv[p * 2 + 1][1] = r[3];
            }
#pragma unroll
            for (int t = 0; t < 8; t++)
                mma16816(o[t], pa[kk], bv[t]);
        }
    }

    // ---- epilogue: normalize, [hi|lo] fp16 split into g_ahat ----
    const float ri0 = 1.f / rs0, ri1 = 1.f / rs1;
    const size_t mrow0 = (size_t)b * S_LEN + qs + mbase + r0;
    __half* row0 = g_ahat + mrow0 * KEFF;
    __half* row1 = row0 + (size_t)8 * KEFF;
    const int kc = h * HD + qcol;
#pragma unroll
    for (int t = 0; t < 8; t++) {
        const int k = kc + t * 8;
        {
            const float v0 = o[t][0] * ri0, v1 = o[t][1] * ri0;
            const float h0 = __half2float(__float2half_rn(v0));
            const float h1 = __half2float(__float2half_rn(v1));
            *(uint32_t*)&row0[k]        = h2pack(v0, v1);
            *(uint32_t*)&row0[1024 + k] = h2pack(v0 - h0, v1 - h1);
        }
        {
            const float v0 = o[t][2] * ri1, v1 = o[t][3] * ri1;
            const float h0 = __half2float(__float2half_rn(v0));
            const float h1 = __half2float(__float2half_rn(v1));
            *(uint32_t*)&row1[k]        = h2pack(v0, v1);
            *(uint32_t*)&row1[1024 + k] = h2pack(v0 - h0, v1 - h1);
        }
    }
}

// ---------------------------------------------------------------------------
extern "C" void kernel_launch(void* const* d_in, const int* in_sizes, int n_in,
                              void* d_out, int out_size)
{
    const float* x      = (const float*)d_in[0];
    const float* w_attn = (const float*)d_in[1];
    const float* b_attn = (const float*)d_in[2];
    const float* w_proj = (const float*)d_in[3];
    const float* b_proj = (const float*)d_in[4];
    float* out = (float*)d_out;
    float* kv  = out + OUT_ELEMS;

    cudaFuncSetAttribute(attn_k, cudaFuncAttributeMaxDynamicSharedMemorySize, ATTN_SMEM_BYTES);
    cudaFuncSetAttribute(gemm_mma<0>, cudaFuncAttributeMaxDynamicSharedMemorySize, GEMM_SMEM);
    cudaFuncSetAttribute(gemm_mma<1>, cudaFuncAttributeMaxDynamicSharedMemorySize, GEMM_SMEM);

    __half *xhat, *ahat, *wat, *wpt;
    cudaGetSymbolAddress((void**)&xhat, g_xhat);
    cudaGetSymbolAddress((void**)&ahat, g_ahat);
    cudaGetSymbolAddress((void**)&wat,  g_wat);
    cudaGetSymbolAddress((void**)&wpt,  g_wpt);

    // 1) split conversions of inputs (fp16 2-term)
    convA_k<<<(TOKENS * 256 + 255) / 256, 256>>>(x, xhat, TOKENS * 256);
    {
        dim3 blk(8, 32);
        convBt_k<<<dim3(3 * D_MODEL / 32, D_MODEL / 32), blk>>>(w_attn, wat, 3 * D_MODEL);
        convBt_k<<<dim3(D_MODEL / 32, D_MODEL / 32),     blk>>>(w_proj, wpt, D_MODEL);
    }

    // 2) QKV projection: fp16 Q/K/V for attention, fp32 K/V -> present tail
    gemm_mma<1><<<dim3(3 * D_MODEL / 128, TOKENS / 128), 256, GEMM_SMEM>>>(
        xhat, wat, b_attn, nullptr, kv);

    // 3) tensor-core flash attention -> g_ahat (fp16 2-term split)
    attn_k<<<BATCH * NH * (S_LEN / 64), 128, ATTN_SMEM_BYTES>>>();

    // 4) output projection -> d_out head
    gemm_mma<0><<<dim3(D_MODEL / 128, TOKENS / 128), 256, GEMM_SMEM>>>(
        ahat, wpt, b_proj, out, nullptr);
}

// round 14
// speedup vs baseline: 2.8133x; 1.3894x over previous
#include <cuda_runtime.h>
#include <cuda_fp16.h>
#include <cstdint>

// Problem constants
#define BATCH   2
#define S_LEN   2048
#define D_MODEL 1024
#define NH      16
#define HD      64
#define WINDOW  256
#define TOKENS  (BATCH * S_LEN)               // 4096
#define OUT_ELEMS ((size_t)TOKENS * D_MODEL)  // 4194304
#define KP      2048                          // proj GEMM K_eff ([Ah|Al].[Bh|Bh])

// ---------------- device scratch (allocation-free rule) ----------------
__device__ __align__(128) __half g_qh [BATCH * NH * S_LEN * HD];     // fp16 Q (pre-scaled)
__device__ __align__(128) __half g_kh [BATCH * NH * S_LEN * HD];     // fp16 K
__device__ __align__(128) __half g_vh [BATCH * NH * S_LEN * HD];     // fp16 V
__device__ __align__(128) __half g_xh  [(size_t)TOKENS * D_MODEL];      // x hi only
__device__ __align__(128) __half g_ahat[(size_t)TOKENS * KP];           // attn out [Ah|Al]
__device__ __align__(128) __half g_wat [(size_t)3 * D_MODEL * D_MODEL]; // w_attn^T hi
__device__ __align__(128) __half g_wpt [(size_t)D_MODEL * KP];          // w_proj^T [Bh|Bh]

// ---------------- helpers ----------------
__device__ __forceinline__ uint32_t smem_u32(const void* p) {
    uint32_t a;
    asm("{ .reg .u64 t; cvta.to.shared.u64 t, %1; cvt.u32.u64 %0, t; }" : "=r"(a) : "l"(p));
    return a;
}
__device__ __forceinline__ void cp16(uint32_t saddr, const void* g) {
    asm volatile("cp.async.cg.shared.global [%0], [%1], 16;" :: "r"(saddr), "l"(g));
}
#define CP_COMMIT() asm volatile("cp.async.commit_group;" ::: "memory")
#define CP_WAIT1()  asm volatile("cp.async.wait_group 1;" ::: "memory")
#define CP_WAIT0()  asm volatile("cp.async.wait_group 0;" ::: "memory")

__device__ __forceinline__ void ldmx4(uint32_t* r, uint32_t addr) {
    asm volatile("ldmatrix.sync.aligned.m8n8.x4.shared.b16 {%0,%1,%2,%3}, [%4];"
                 : "=r"(r[0]), "=r"(r[1]), "=r"(r[2]), "=r"(r[3]) : "r"(addr));
}
__device__ __forceinline__ void ldmx4t(uint32_t* r, uint32_t addr) {
    asm volatile("ldmatrix.sync.aligned.m8n8.x4.trans.shared.b16 {%0,%1,%2,%3}, [%4];"
                 : "=r"(r[0]), "=r"(r[1]), "=r"(r[2]), "=r"(r[3]) : "r"(addr));
}
__device__ __forceinline__ void mma16816(float* c, const uint32_t* a, const uint32_t* b) {
    asm volatile(
        "mma.sync.aligned.m16n8k16.row.col.f32.f16.f16.f32 "
        "{%0,%1,%2,%3}, {%4,%5,%6,%7}, {%8,%9}, {%0,%1,%2,%3};"
        : "+f"(c[0]), "+f"(c[1]), "+f"(c[2]), "+f"(c[3])
        : "r"(a[0]), "r"(a[1]), "r"(a[2]), "r"(a[3]), "r"(b[0]), "r"(b[1]));
}
__device__ __forceinline__ uint32_t h2pack(float a, float b) {
    __half2 t = __floats2half2_rn(a, b);
    return *reinterpret_cast<uint32_t*>(&t);
}

// ---------------- conversion kernels ----------------
// fp32 [M,1024] -> fp16 hi only [M,1024]
__global__ void convAh_k(const float* __restrict__ A, __half* __restrict__ O, int total4)
{
    int idx = blockIdx.x * blockDim.x + threadIdx.x;
    if (idx >= total4) return;
    float4 v = *(const float4*)&A[(size_t)idx * 4];
    uint2 H = {h2pack(v.x, v.y), h2pack(v.z, v.w)};
    *(uint2*)&O[(size_t)idx * 4] = H;
}
// W fp32 [1024, N] -> W^T fp16 hi [N, 1024] (transpose)
__global__ void convBth_k(const float* __restrict__ W, __half* __restrict__ O, int N)
{
    __shared__ float tile[32][33];
    const int k0 = blockIdx.y * 32, n0 = blockIdx.x * 32;
    const int tx = threadIdx.x;   // 0..7
    const int ty = threadIdx.y;   // 0..31
    float4 w4 = *(const float4*)&W[(size_t)(k0 + ty) * N + n0 + tx * 4];
    tile[ty][tx * 4 + 0] = w4.x;
    tile[ty][tx * 4 + 1] = w4.y;
    tile[ty][tx * 4 + 2] = w4.z;
    tile[ty][tx * 4 + 3] = w4.w;
    __syncthreads();
    const int tid = ty * 8 + tx;
    const int nr = tid >> 3;
    const int kq = tid & 7;
    uint2 H = {h2pack(tile[kq * 4 + 0][nr], tile[kq * 4 + 1][nr]),
               h2pack(tile[kq * 4 + 2][nr], tile[kq * 4 + 3][nr])};
    *(uint2*)&O[(size_t)(n0 + nr) * D_MODEL + k0 + kq * 4] = H;
}
// W fp32 [1024, N] -> W^T fp16 [N, 2048] segments [hi | hi] (proj weights)
__global__ void convBt2_k(const float* __restrict__ W, __half* __restrict__ O, int N)
{
    __shared__ float tile[32][33];
    const int k0 = blockIdx.y * 32, n0 = blockIdx.x * 32;
    const int tx = threadIdx.x;
    const int ty = threadIdx.y;
    float4 w4 = *(const float4*)&W[(size_t)(k0 + ty) * N + n0 + tx * 4];
    tile[ty][tx * 4 + 0] = w4.x;
    tile[ty][tx * 4 + 1] = w4.y;
    tile[ty][tx * 4 + 2] = w4.z;
    tile[ty][tx * 4 + 3] = w4.w;
    __syncthreads();
    const int tid = ty * 8 + tx;
    const int nr = tid >> 3;
    const int kq = tid & 7;
    uint2 H = {h2pack(tile[kq * 4 + 0][nr], tile[kq * 4 + 1][nr]),
               h2pack(tile[kq * 4 + 2][nr], tile[kq * 4 + 3][nr])};
    __half* row = O + (size_t)(n0 + nr) * KP;
    const int k = k0 + kq * 4;
    *(uint2*)&row[k]        = H;
    *(uint2*)&row[1024 + k] = H;
}

// ---------------- mma.sync GEMM (R12 structure; K length templated) ----------------
#define TILE_BYTES  18432
#define BUF_BYTES   36864
#define GEMM_SMEM   110592

template<int MODE, int KEL>
__global__ __launch_bounds__(256, 2) void gemm_mma(const __half* __restrict__ A,
                                                   const __half* __restrict__ Bt,
                                                   const float* __restrict__ bias,
                                                   float* __restrict__ C,
                                                   float* __restrict__ KV)
{
    constexpr int NCH = KEL / 64;
    extern __shared__ char smem[];
    const uint32_t sb = smem_u32(smem);
    const int tid = threadIdx.x;
    const int wid = tid >> 5, lid = tid & 31;
    const int m0 = blockIdx.y * 128, n0 = blockIdx.x * 128;
    const int mbase = (wid & 1) * 64;
    const int nbase = (wid >> 1) * 32;

    const char* Abase = (const char*)(A  + (size_t)m0 * KEL);
    const char* Bbase = (const char*)(Bt + (size_t)n0 * KEL);

    const uint32_t a_row_off = (uint32_t)((mbase + ((lid >> 3) & 1) * 8 + (lid & 7)) * 144
                                          + ((lid >> 4) * 8) * 2);
    const uint32_t b_row_off = (uint32_t)((nbase + ((lid >> 4) & 1) * 8 + (lid & 7)) * 144
                                          + (((lid >> 3) & 1) * 8) * 2);

    float acc[4][4][4];
#pragma unroll
    for (int mt = 0; mt < 4; mt++)
#pragma unroll
        for (int nt = 0; nt < 4; nt++)
#pragma unroll
            for (int i = 0; i < 4; i++) acc[mt][nt][i] = 0.f;

#define PREFETCH(c, buf)                                                          \
    {                                                                             \
        const size_t kbyte = (size_t)(c) * 128;                                   \
        const uint32_t abuf = sb + (buf) * BUF_BYTES;                             \
        const uint32_t bbuf = abuf + TILE_BYTES;                                  \
        _Pragma("unroll")                                                         \
        for (int i = 0; i < 4; i++) {                                             \
            int idx = tid + i * 256;                                              \
            int row = idx >> 3, seg = idx & 7;                                    \
            uint32_t so = row * 144 + seg * 16;                                   \
            cp16(abuf + so, Abase + (size_t)row * (KEL * 2) + kbyte + seg * 16);  \
            cp16(bbuf + so, Bbase + (size_t)row * (KEL * 2) + kbyte + seg * 16);  \
        }                                                                         \
    }

    PREFETCH(0, 0); CP_COMMIT();
    PREFETCH(1, 1); CP_COMMIT();

    int buf = 0;
    for (int c = 0; c < NCH; c++) {
        if (c == NCH - 1) { CP_WAIT0(); } else { CP_WAIT1(); }
        __syncthreads();
        if (c + 2 < NCH) {
            int nbuf = buf + 2; if (nbuf >= 3) nbuf -= 3;
            PREFETCH(c + 2, nbuf);
            CP_COMMIT();
        }
        const uint32_t abuf = sb + buf * BUF_BYTES;
        const uint32_t bbuf = abuf + TILE_BYTES;
#pragma unroll
        for (int ks = 0; ks < 4; ks++) {
            const uint32_t kb = (uint32_t)ks * 32;
            uint32_t ar[4][4];
            uint32_t br[4][2];
#pragma unroll
            for (int mt = 0; mt < 4; mt++)
                ldmx4(ar[mt], abuf + a_row_off + mt * (16 * 144) + kb);
#pragma unroll
            for (int p = 0; p < 2; p++) {
                uint32_t r[4];
                ldmx4(r, bbuf + b_row_off + p * (16 * 144) + kb);
                br[p * 2][0] = r[0]; br[p * 2][1] = r[1];
                br[p * 2 + 1][0] = r[2]; br[p * 2 + 1][1] = r[3];
            }
#pragma unroll
            for (int mt = 0; mt < 4; mt++)
#pragma unroll
                for (int nt = 0; nt < 4; nt++)
                    mma16816(acc[mt][nt], ar[mt], br[nt]);
        }
        if (++buf == 3) buf = 0;
    }
#undef PREFETCH

    const int lrow = lid >> 2;
    const int lcol = (lid & 3) * 2;
#pragma unroll
    for (int mt = 0; mt < 4; mt++) {
        const int gm = m0 + mbase + mt * 16 + lrow;
#pragma unroll
        for (int nt = 0; nt < 4; nt++) {
            const int gn = n0 + nbase + nt * 8 + lcol;
            if (MODE == 0) {
                const float b0 = bias[gn], b1 = bias[gn + 1];
                float2 v0 = {acc[mt][nt][0] + b0, acc[mt][nt][1] + b1};
                float2 v1 = {acc[mt][nt][2] + b0, acc[mt][nt][3] + b1};
                *(float2*)&C[(size_t)gm * D_MODEL + gn] = v0;
                *(float2*)&C[(size_t)(gm + 8) * D_MODEL + gn] = v1;
            } else {
                const float b0 = bias[gn], b1 = bias[gn + 1];
                const int sec = gn >> 10, fr = gn & 1023;
                const int hh = fr >> 6, dd = fr & 63;
#pragma unroll
                for (int e2 = 0; e2 < 2; e2++) {
                    const int row = gm + e2 * 8;
                    const int bb = row >> 11, s = row & 2047;
                    float2 w = {acc[mt][nt][e2 * 2 + 0] + b0,
                                acc[mt][nt][e2 * 2 + 1] + b1};
                    const size_t base = (((size_t)bb * NH + hh) * S_LEN + s) * HD + dd;
                    if (sec == 0) {
                        *(uint32_t*)&g_qh[base] = h2pack(w.x * 0.125f, w.y * 0.125f);
                    } else {
                        const size_t kvb =
                            ((((size_t)bb * 2 + (sec - 1)) * NH + hh) * S_LEN + s) * HD + dd;
                        *(float2*)&KV[kvb] = w;    // fp32 `present`
                        if (sec == 1) *(uint32_t*)&g_kh[base] = h2pack(w.x, w.y);
                        else          *(uint32_t*)&g_vh[base] = h2pack(w.x, w.y);
                    }
                }
            }
        }
    }
}

// ---------------- tensor-core flash attention (unchanged from R13 winner) ----------------
#define ATTN_SMEM_BYTES (3 * 64 * 144)

__global__ __launch_bounds__(128, 4) void attn_k()
{
    extern __shared__ char smem[];
    const uint32_t sb = smem_u32(smem);
    const uint32_t sQ = sb, sK = sb + 9216, sV = sb + 18432;

    const int bid = blockIdx.x;
    const int qt = bid & 31;
    const int h  = (bid >> 5) & 15;
    const int b  = bid >> 9;
    const int qs = qt * 64;

    const int tid = threadIdx.x;
    const int wid = tid >> 5, lid = tid & 31;
    const int mbase = wid * 16;

    const __half* Qg = g_qh + ((size_t)(b * NH + h) * S_LEN + qs) * HD;
    const __half* Kg = g_kh + ((size_t)(b * NH + h) * S_LEN) * HD;
    const __half* Vg = g_vh + ((size_t)(b * NH + h) * S_LEN) * HD;

    for (int idx = tid; idx < 512; idx += 128) {
        const int row = idx >> 3, seg = idx & 7;
        cp16(sQ + row * 144 + seg * 16, (const char*)Qg + row * 128 + seg * 16);
    }
    CP_COMMIT();

    const uint32_t a_off = (uint32_t)((mbase + ((lid >> 3) & 1) * 8 + (lid & 7)) * 144
                                      + ((lid >> 4) * 8) * 2);
    const uint32_t bK_off = (uint32_t)(((((lid >> 4) & 1) * 8) + (lid & 7)) * 144
                                       + (((lid >> 3) & 1) * 8) * 2);
    const int vmid = lid >> 3;
    const uint32_t bV_off = (uint32_t)((((vmid & 1) * 8 + (lid & 7)) * 144)
                                       + ((vmid >> 1) * 8) * 2);

    const int r0 = lid >> 2;
    const int qcol = (lid & 3) * 2;

    float o[8][4];
#pragma unroll
    for (int t = 0; t < 8; t++)
#pragma unroll
        for (int i = 0; i < 4; i++) o[t][i] = 0.f;
    float m0r = -1e29f, m1r = -1e29f, rs0 = 0.f, rs1 = 0.f;

    for (int kt = 0; kt < 5; kt++) {
        const int ks = qs - 256 + kt * 64;
        if (ks + 64 <= 0) continue;

        __syncthreads();
        for (int idx = tid; idx < 512; idx += 128) {
            const int row = idx >> 3, seg = idx & 7;
            const int gj = ks + row;
            if (gj >= 0) {
                cp16(sK + row * 144 + seg * 16, (const char*)Kg + (size_t)gj * 128 + seg * 16);
                cp16(sV + row * 144 + seg * 16, (const char*)Vg + (size_t)gj * 128 + seg * 16);
            } else {
                uint4 z = {0u, 0u, 0u, 0u};
                *(uint4*)(smem + 9216  + row * 144 + seg * 16) = z;
                *(uint4*)(smem + 18432 + row * 144 + seg * 16) = z;
            }
        }
        CP_COMMIT();
        CP_WAIT0();
        __syncthreads();

        float c[8][4];
#pragma unroll
        for (int t = 0; t < 8; t++)
#pragma unroll
            for (int i = 0; i < 4; i++) c[t][i] = 0.f;
#pragma unroll
        for (int ks4 = 0; ks4 < 4; ks4++) {
            const uint32_t kb = (uint32_t)ks4 * 32;
            uint32_t aq[4];
            ldmx4(aq, sQ + a_off + kb);
            uint32_t bk[8][2];
#pragma unroll
            for (int p = 0; p < 4; p++) {
                uint32_t r[4];
                ldmx4(r, sK + bK_off + p * (16 * 144) + kb);
                bk[p * 2][0] = r[0]; bk[p * 2][1] = r[1];
                bk[p * 2 + 1][0] = r[2]; bk[p * 2 + 1][1] = r[3];
            }
#pragma unroll
            for (int t = 0; t < 8; t++)
                mma16816(c[t], aq, bk[t]);
        }

        const int gi0 = qs + mbase + r0, gi1 = gi0 + 8;
#pragma unroll
        for (int t = 0; t < 8; t++) {
            const int cb = ks + t * 8 + qcol;
#pragma unroll
            for (int e = 0; e < 2; e++) {
                const int gj = cb + e;
                if (!(gj >= 0 && gj <= gi0 && gj > gi0 - WINDOW)) c[t][e]     = -1e30f;
                if (!(gj >= 0 && gj <= gi1 && gj > gi1 - WINDOW)) c[t][e + 2] = -1e30f;
            }
        }

        float mx0 = -1e30f, mx1 = -1e30f;
#pragma unroll
        for (int t = 0; t < 8; t++) {
            mx0 = fmaxf(mx0, fmaxf(c[t][0], c[t][1]));
            mx1 = fmaxf(mx1, fmaxf(c[t][2], c[t][3]));
        }
#pragma unroll
        for (int w = 1; w < 4; w <<= 1) {
            mx0 = fmaxf(mx0, __shfl_xor_sync(0xffffffffu, mx0, w));
            mx1 = fmaxf(mx1, __shfl_xor_sync(0xffffffffu, mx1, w));
        }
        const float mn0 = fmaxf(m0r, mx0), mn1 = fmaxf(m1r, mx1);
        const float al0 = __expf(m0r - mn0), al1 = __expf(m1r - mn1);

        uint32_t pa[4][4];
        float ls0 = 0.f, ls1 = 0.f;
#pragma unroll
        for (int t = 0; t < 8; t++) {
            const float p0 = __expf(c[t][0] - mn0);
            const float p1 = __expf(c[t][1] - mn0);
            const float p2 = __expf(c[t][2] - mn1);
            const float p3 = __expf(c[t][3] - mn1);
            ls0 += p0 + p1; ls1 += p2 + p3;
            pa[t >> 1][(t & 1) * 2 + 0] = h2pack(p0, p1);
            pa[t >> 1][(t & 1) * 2 + 1] = h2pack(p2, p3);
        }
#pragma unroll
        for (int w = 1; w < 4; w <<= 1) {
            ls0 += __shfl_xor_sync(0xffffffffu, ls0, w);
            ls1 += __shfl_xor_sync(0xffffffffu, ls1, w);
        }
        rs0 = rs0 * al0 + ls0;
        rs1 = rs1 * al1 + ls1;
        m0r = mn0; m1r = mn1;
#pragma unroll
        for (int t = 0; t < 8; t++) {
            o[t][0] *= al0; o[t][1] *= al0;
            o[t][2] *= al1; o[t][3] *= al1;
        }

#pragma unroll
        for (int kk = 0; kk < 4; kk++) {
            uint32_t bv[8][2];
#pragma unroll
            for (int p = 0; p < 4; p++) {
                uint32_t r[4];
                ldmx4t(r, sV + bV_off + kk * (16 * 144) + p * 32);
                bv[p * 2][0] = r[0]; bv[p * 2][1] = r[1];
                bv[p * 2 + 1][0] = r[2]; bv[p * 2 + 1][1] = r[3];
            }
#pragma unroll
            for (int t = 0; t < 8; t++)
                mma16816(o[t], pa[kk], bv[t]);
        }
    }

    const float ri0 = 1.f / rs0, ri1 = 1.f / rs1;
    const size_t mrow0 = (size_t)b * S_LEN + qs + mbase + r0;
    __half* row0 = g_ahat + mrow0 * KP;
    __half* row1 = row0 + (size_t)8 * KP;
    const int kc = h * HD + qcol;
#pragma unroll
    for (int t = 0; t < 8; t++) {
        const int k = kc + t * 8;
        {
            const float v0 = o[t][0] * ri0, v1 = o[t][1] * ri0;
            const float h0 = __half2float(__float2half_rn(v0));
            const float h1 = __half2float(__float2half_rn(v1));
            *(uint32_t*)&row0[k]        = h2pack(v0, v1);
            *(uint32_t*)&row0[1024 + k] = h2pack(v0 - h0, v1 - h1);
        }
        {
            const float v0 = o[t][2] * ri1, v1 = o[t][3] * ri1;
            const float h0 = __half2float(__float2half_rn(v0));
            const float h1 = __half2float(__float2half_rn(v1));
            *(uint32_t*)&row1[k]        = h2pack(v0, v1);
            *(uint32_t*)&row1[1024 + k] = h2pack(v0 - h0, v1 - h1);
        }
    }
}

// ---------------------------------------------------------------------------
extern "C" void kernel_launch(void* const* d_in, const int* in_sizes, int n_in,
                              void* d_out, int out_size)
{
    const float* x      = (const float*)d_in[0];
    const float* w_attn = (const float*)d_in[1];
    const float* b_attn = (const float*)d_in[2];
    const float* w_proj = (const float*)d_in[3];
    const float* b_proj = (const float*)d_in[4];
    float* out = (float*)d_out;
    float* kv  = out + OUT_ELEMS;

    cudaFuncSetAttribute(attn_k, cudaFuncAttributeMaxDynamicSharedMemorySize, ATTN_SMEM_BYTES);
    cudaFuncSetAttribute((gemm_mma<0, KP>), cudaFuncAttributeMaxDynamicSharedMemorySize, GEMM_SMEM);
    cudaFuncSetAttribute((gemm_mma<1, 1024>), cudaFuncAttributeMaxDynamicSharedMemorySize, GEMM_SMEM);

    __half *xh, *ahat, *wat, *wpt;
    cudaGetSymbolAddress((void**)&xh,   g_xh);
    cudaGetSymbolAddress((void**)&ahat, g_ahat);
    cudaGetSymbolAddress((void**)&wat,  g_wat);
    cudaGetSymbolAddress((void**)&wpt,  g_wpt);

    // 1) conversions: x -> fp16 hi; w_attn^T -> fp16 hi; w_proj^T -> [hi|hi]
    convAh_k<<<(TOKENS * 256 + 255) / 256, 256>>>(x, xh, TOKENS * 256);
    {
        dim3 blk(8, 32);
        convBth_k<<<dim3(3 * D_MODEL / 32, D_MODEL / 32), blk>>>(w_attn, wat, 3 * D_MODEL);
        convBt2_k<<<dim3(D_MODEL / 32, D_MODEL / 32),     blk>>>(w_proj, wpt, D_MODEL);
    }

    // 2) QKV projection (K=1024, 1-term): fp16 Q/K/V + fp32 present tail
    gemm_mma<1, 1024><<<dim3(3 * D_MODEL / 128, TOKENS / 128), 256, GEMM_SMEM>>>(
        xh, wat, b_attn, nullptr, kv);

    // 3) tensor-core flash attention -> g_ahat ([hi|lo] split)
    attn_k<<<BATCH * NH * (S_LEN / 64), 128, ATTN_SMEM_BYTES>>>();

    // 4) output projection (K_eff=2048, 2-term) -> d_out head
    gemm_mma<0, KP><<<dim3(D_MODEL / 128, TOKENS / 128), 256, GEMM_SMEM>>>(
        ahat, wpt, b_proj, out, nullptr);
}

// round 15
// speedup vs baseline: 3.3100x; 1.1765x over previous
#include <cuda_runtime.h>
#include <cuda_fp16.h>
#include <cstdint>

// Problem constants
#define BATCH   2
#define S_LEN   2048
#define D_MODEL 1024
#define NH      16
#define HD      64
#define WINDOW  256
#define TOKENS  (BATCH * S_LEN)               // 4096
#define OUT_ELEMS ((size_t)TOKENS * D_MODEL)  // 4194304

// ---------------- device scratch (allocation-free rule) ----------------
__device__ __align__(128) __half g_qh [BATCH * NH * S_LEN * HD];     // fp16 Q (pre-scaled)
__device__ __align__(128) __half g_kh [BATCH * NH * S_LEN * HD];     // fp16 K
__device__ __align__(128) __half g_vh [BATCH * NH * S_LEN * HD];     // fp16 V
__device__ __align__(128) __half g_xh  [(size_t)TOKENS * D_MODEL];      // x hi
__device__ __align__(128) __half g_ah  [(size_t)TOKENS * D_MODEL];      // attn out hi
__device__ __align__(128) __half g_wat [(size_t)3 * D_MODEL * D_MODEL]; // w_attn^T hi
__device__ __align__(128) __half g_wpt [(size_t)D_MODEL * D_MODEL];     // w_proj^T hi

// ---------------- helpers ----------------
__device__ __forceinline__ uint32_t smem_u32(const void* p) {
    uint32_t a;
    asm("{ .reg .u64 t; cvta.to.shared.u64 t, %1; cvt.u32.u64 %0, t; }" : "=r"(a) : "l"(p));
    return a;
}
__device__ __forceinline__ void cp16(uint32_t saddr, const void* g) {
    asm volatile("cp.async.cg.shared.global [%0], [%1], 16;" :: "r"(saddr), "l"(g));
}
#define CP_COMMIT() asm volatile("cp.async.commit_group;" ::: "memory")
#define CP_WAIT1()  asm volatile("cp.async.wait_group 1;" ::: "memory")
#define CP_WAIT0()  asm volatile("cp.async.wait_group 0;" ::: "memory")

__device__ __forceinline__ void ldmx4(uint32_t* r, uint32_t addr) {
    asm volatile("ldmatrix.sync.aligned.m8n8.x4.shared.b16 {%0,%1,%2,%3}, [%4];"
                 : "=r"(r[0]), "=r"(r[1]), "=r"(r[2]), "=r"(r[3]) : "r"(addr));
}
__device__ __forceinline__ void ldmx4t(uint32_t* r, uint32_t addr) {
    asm volatile("ldmatrix.sync.aligned.m8n8.x4.trans.shared.b16 {%0,%1,%2,%3}, [%4];"
                 : "=r"(r[0]), "=r"(r[1]), "=r"(r[2]), "=r"(r[3]) : "r"(addr));
}
__device__ __forceinline__ void mma16816(float* c, const uint32_t* a, const uint32_t* b) {
    asm volatile(
        "mma.sync.aligned.m16n8k16.row.col.f32.f16.f16.f32 "
        "{%0,%1,%2,%3}, {%4,%5,%6,%7}, {%8,%9}, {%0,%1,%2,%3};"
        : "+f"(c[0]), "+f"(c[1]), "+f"(c[2]), "+f"(c[3])
        : "r"(a[0]), "r"(a[1]), "r"(a[2]), "r"(a[3]), "r"(b[0]), "r"(b[1]));
}
__device__ __forceinline__ uint32_t h2pack(float a, float b) {
    __half2 t = __floats2half2_rn(a, b);
    return *reinterpret_cast<uint32_t*>(&t);
}

// ---------------- conversion kernels ----------------
// fp32 [M,1024] -> fp16 hi [M,1024]
__global__ void convAh_k(const float* __restrict__ A, __half* __restrict__ O, int total4)
{
    int idx = blockIdx.x * blockDim.x + threadIdx.x;
    if (idx >= total4) return;
    float4 v = *(const float4*)&A[(size_t)idx * 4];
    uint2 H = {h2pack(v.x, v.y), h2pack(v.z, v.w)};
    *(uint2*)&O[(size_t)idx * 4] = H;
}
// W fp32 [1024, N] -> W^T fp16 hi [N, 1024] (transpose)
__global__ void convBth_k(const float* __restrict__ W, __half* __restrict__ O, int N)
{
    __shared__ float tile[32][33];
    const int k0 = blockIdx.y * 32, n0 = blockIdx.x * 32;
    const int tx = threadIdx.x;   // 0..7
    const int ty = threadIdx.y;   // 0..31
    float4 w4 = *(const float4*)&W[(size_t)(k0 + ty) * N + n0 + tx * 4];
    tile[ty][tx * 4 + 0] = w4.x;
    tile[ty][tx * 4 + 1] = w4.y;
    tile[ty][tx * 4 + 2] = w4.z;
    tile[ty][tx * 4 + 3] = w4.w;
    __syncthreads();
    const int tid = ty * 8 + tx;
    const int nr = tid >> 3;
    const int kq = tid & 7;
    uint2 H = {h2pack(tile[kq * 4 + 0][nr], tile[kq * 4 + 1][nr]),
               h2pack(tile[kq * 4 + 2][nr], tile[kq * 4 + 3][nr])};
    *(uint2*)&O[(size_t)(n0 + nr) * D_MODEL + k0 + kq * 4] = H;
}

// ---------------- mma.sync GEMM (K = 1024 for both modes now) ----------------
#define TILE_BYTES  18432
#define BUF_BYTES   36864
#define GEMM_SMEM   110592
#define KEL         1024
#define NCH         16

template<int MODE>
__global__ __launch_bounds__(256, 2) void gemm_mma(const __half* __restrict__ A,
                                                   const __half* __restrict__ Bt,
                                                   const float* __restrict__ bias,
                                                   float* __restrict__ C,
                                                   float* __restrict__ KV)
{
    extern __shared__ char smem[];
    const uint32_t sb = smem_u32(smem);
    const int tid = threadIdx.x;
    const int wid = tid >> 5, lid = tid & 31;
    const int m0 = blockIdx.y * 128, n0 = blockIdx.x * 128;
    const int mbase = (wid & 1) * 64;
    const int nbase = (wid >> 1) * 32;

    const char* Abase = (const char*)(A  + (size_t)m0 * KEL);
    const char* Bbase = (const char*)(Bt + (size_t)n0 * KEL);

    const uint32_t a_row_off = (uint32_t)((mbase + ((lid >> 3) & 1) * 8 + (lid & 7)) * 144
                                          + ((lid >> 4) * 8) * 2);
    const uint32_t b_row_off = (uint32_t)((nbase + ((lid >> 4) & 1) * 8 + (lid & 7)) * 144
                                          + (((lid >> 3) & 1) * 8) * 2);

    float acc[4][4][4];
#pragma unroll
    for (int mt = 0; mt < 4; mt++)
#pragma unroll
        for (int nt = 0; nt < 4; nt++)
#pragma unroll
            for (int i = 0; i < 4; i++) acc[mt][nt][i] = 0.f;

#define PREFETCH(c, buf)                                                          \
    {                                                                             \
        const size_t kbyte = (size_t)(c) * 128;                                   \
        const uint32_t abuf = sb + (buf) * BUF_BYTES;                             \
        const uint32_t bbuf = abuf + TILE_BYTES;                                  \
        _Pragma("unroll")                                                         \
        for (int i = 0; i < 4; i++) {                                             \
            int idx = tid + i * 256;                                              \
            int row = idx >> 3, seg = idx & 7;                                    \
            uint32_t so = row * 144 + seg * 16;                                   \
            cp16(abuf + so, Abase + (size_t)row * (KEL * 2) + kbyte + seg * 16);  \
            cp16(bbuf + so, Bbase + (size_t)row * (KEL * 2) + kbyte + seg * 16);  \
        }                                                                         \
    }

    PREFETCH(0, 0); CP_COMMIT();
    PREFETCH(1, 1); CP_COMMIT();

    int buf = 0;
    for (int c = 0; c < NCH; c++) {
        if (c == NCH - 1) { CP_WAIT0(); } else { CP_WAIT1(); }
        __syncthreads();
        if (c + 2 < NCH) {
            int nbuf = buf + 2; if (nbuf >= 3) nbuf -= 3;
            PREFETCH(c + 2, nbuf);
            CP_COMMIT();
        }
        const uint32_t abuf = sb + buf * BUF_BYTES;
        const uint32_t bbuf = abuf + TILE_BYTES;
#pragma unroll
        for (int ks = 0; ks < 4; ks++) {
            const uint32_t kb = (uint32_t)ks * 32;
            uint32_t ar[4][4];
            uint32_t br[4][2];
#pragma unroll
            for (int mt = 0; mt < 4; mt++)
                ldmx4(ar[mt], abuf + a_row_off + mt * (16 * 144) + kb);
#pragma unroll
            for (int p = 0; p < 2; p++) {
                uint32_t r[4];
                ldmx4(r, bbuf + b_row_off + p * (16 * 144) + kb);
                br[p * 2][0] = r[0]; br[p * 2][1] = r[1];
                br[p * 2 + 1][0] = r[2]; br[p * 2 + 1][1] = r[3];
            }
#pragma unroll
            for (int mt = 0; mt < 4; mt++)
#pragma unroll
                for (int nt = 0; nt < 4; nt++)
                    mma16816(acc[mt][nt], ar[mt], br[nt]);
        }
        if (++buf == 3) buf = 0;
    }
#undef PREFETCH

    const int lrow = lid >> 2;
    const int lcol = (lid & 3) * 2;
#pragma unroll
    for (int mt = 0; mt < 4; mt++) {
        const int gm = m0 + mbase + mt * 16 + lrow;
#pragma unroll
        for (int nt = 0; nt < 4; nt++) {
            const int gn = n0 + nbase + nt * 8 + lcol;
            if (MODE == 0) {
                const float b0 = bias[gn], b1 = bias[gn + 1];
                float2 v0 = {acc[mt][nt][0] + b0, acc[mt][nt][1] + b1};
                float2 v1 = {acc[mt][nt][2] + b0, acc[mt][nt][3] + b1};
                *(float2*)&C[(size_t)gm * D_MODEL + gn] = v0;
                *(float2*)&C[(size_t)(gm + 8) * D_MODEL + gn] = v1;
            } else {
                const float b0 = bias[gn], b1 = bias[gn + 1];
                const int sec = gn >> 10, fr = gn & 1023;
                const int hh = fr >> 6, dd = fr & 63;
#pragma unroll
                for (int e2 = 0; e2 < 2; e2++) {
                    const int row = gm + e2 * 8;
                    const int bb = row >> 11, s = row & 2047;
                    float2 w = {acc[mt][nt][e2 * 2 + 0] + b0,
                                acc[mt][nt][e2 * 2 + 1] + b1};
                    const size_t base = (((size_t)bb * NH + hh) * S_LEN + s) * HD + dd;
                    if (sec == 0) {
                        *(uint32_t*)&g_qh[base] = h2pack(w.x * 0.125f, w.y * 0.125f);
                    } else {
                        const size_t kvb =
                            ((((size_t)bb * 2 + (sec - 1)) * NH + hh) * S_LEN + s) * HD + dd;
                        *(float2*)&KV[kvb] = w;    // fp32 `present`
                        if (sec == 1) *(uint32_t*)&g_kh[base] = h2pack(w.x, w.y);
                        else          *(uint32_t*)&g_vh[base] = h2pack(w.x, w.y);
                    }
                }
            }
        }
    }
}

// ---------------- tensor-core flash attention (R13 winner; hi-only epilogue) ----------------
#define ATTN_SMEM_BYTES (3 * 64 * 144)

__global__ __launch_bounds__(128, 4) void attn_k()
{
    extern __shared__ char smem[];
    const uint32_t sb = smem_u32(smem);
    const uint32_t sQ = sb, sK = sb + 9216, sV = sb + 18432;

    const int bid = blockIdx.x;
    const int qt = bid & 31;
    const int h  = (bid >> 5) & 15;
    const int b  = bid >> 9;
    const int qs = qt * 64;

    const int tid = threadIdx.x;
    const int wid = tid >> 5, lid = tid & 31;
    const int mbase = wid * 16;

    const __half* Qg = g_qh + ((size_t)(b * NH + h) * S_LEN + qs) * HD;
    const __half* Kg = g_kh + ((size_t)(b * NH + h) * S_LEN) * HD;
    const __half* Vg = g_vh + ((size_t)(b * NH + h) * S_LEN) * HD;

    for (int idx = tid; idx < 512; idx += 128) {
        const int row = idx >> 3, seg = idx & 7;
        cp16(sQ + row * 144 + seg * 16, (const char*)Qg + row * 128 + seg * 16);
    }
    CP_COMMIT();

    const uint32_t a_off = (uint32_t)((mbase + ((lid >> 3) & 1) * 8 + (lid & 7)) * 144
                                      + ((lid >> 4) * 8) * 2);
    const uint32_t bK_off = (uint32_t)(((((lid >> 4) & 1) * 8) + (lid & 7)) * 144
                                       + (((lid >> 3) & 1) * 8) * 2);
    const int vmid = lid >> 3;
    const uint32_t bV_off = (uint32_t)((((vmid & 1) * 8 + (lid & 7)) * 144)
                                       + ((vmid >> 1) * 8) * 2);

    const int r0 = lid >> 2;
    const int qcol = (lid & 3) * 2;

    float o[8][4];
#pragma unroll
    for (int t = 0; t < 8; t++)
#pragma unroll
        for (int i = 0; i < 4; i++) o[t][i] = 0.f;
    float m0r = -1e29f, m1r = -1e29f, rs0 = 0.f, rs1 = 0.f;

    for (int kt = 0; kt < 5; kt++) {
        const int ks = qs - 256 + kt * 64;
        if (ks + 64 <= 0) continue;

        __syncthreads();
        for (int idx = tid; idx < 512; idx += 128) {
            const int row = idx >> 3, seg = idx & 7;
            const int gj = ks + row;
            if (gj >= 0) {
                cp16(sK + row * 144 + seg * 16, (const char*)Kg + (size_t)gj * 128 + seg * 16);
                cp16(sV + row * 144 + seg * 16, (const char*)Vg + (size_t)gj * 128 + seg * 16);
            } else {
                uint4 z = {0u, 0u, 0u, 0u};
                *(uint4*)(smem + 9216  + row * 144 + seg * 16) = z;
                *(uint4*)(smem + 18432 + row * 144 + seg * 16) = z;
            }
        }
        CP_COMMIT();
        CP_WAIT0();
        __syncthreads();

        float c[8][4];
#pragma unroll
        for (int t = 0; t < 8; t++)
#pragma unroll
            for (int i = 0; i < 4; i++) c[t][i] = 0.f;
#pragma unroll
        for (int ks4 = 0; ks4 < 4; ks4++) {
            const uint32_t kb = (uint32_t)ks4 * 32;
            uint32_t aq[4];
            ldmx4(aq, sQ + a_off + kb);
            uint32_t bk[8][2];
#pragma unroll
            for (int p = 0; p < 4; p++) {
                uint32_t r[4];
                ldmx4(r, sK + bK_off + p * (16 * 144) + kb);
                bk[p * 2][0] = r[0]; bk[p * 2][1] = r[1];
                bk[p * 2 + 1][0] = r[2]; bk[p * 2 + 1][1] = r[3];
            }
#pragma unroll
            for (int t = 0; t < 8; t++)
                mma16816(c[t], aq, bk[t]);
        }

        const int gi0 = qs + mbase + r0, gi1 = gi0 + 8;
#pragma unroll
        for (int t = 0; t < 8; t++) {
            const int cb = ks + t * 8 + qcol;
#pragma unroll
            for (int e = 0; e < 2; e++) {
                const int gj = cb + e;
                if (!(gj >= 0 && gj <= gi0 && gj > gi0 - WINDOW)) c[t][e]     = -1e30f;
                if (!(gj >= 0 && gj <= gi1 && gj > gi1 - WINDOW)) c[t][e + 2] = -1e30f;
            }
        }

        float mx0 = -1e30f, mx1 = -1e30f;
#pragma unroll
        for (int t = 0; t < 8; t++) {
            mx0 = fmaxf(mx0, fmaxf(c[t][0], c[t][1]));
            mx1 = fmaxf(mx1, fmaxf(c[t][2], c[t][3]));
        }
#pragma unroll
        for (int w = 1; w < 4; w <<= 1) {
            mx0 = fmaxf(mx0, __shfl_xor_sync(0xffffffffu, mx0, w));
            mx1 = fmaxf(mx1, __shfl_xor_sync(0xffffffffu, mx1, w));
        }
        const float mn0 = fmaxf(m0r, mx0), mn1 = fmaxf(m1r, mx1);
        const float al0 = __expf(m0r - mn0), al1 = __expf(m1r - mn1);

        uint32_t pa[4][4];
        float ls0 = 0.f, ls1 = 0.f;
#pragma unroll
        for (int t = 0; t < 8; t++) {
            const float p0 = __expf(c[t][0] - mn0);
            const float p1 = __expf(c[t][1] - mn0);
            const float p2 = __expf(c[t][2] - mn1);
            const float p3 = __expf(c[t][3] - mn1);
            ls0 += p0 + p1; ls1 += p2 + p3;
            pa[t >> 1][(t & 1) * 2 + 0] = h2pack(p0, p1);
            pa[t >> 1][(t & 1) * 2 + 1] = h2pack(p2, p3);
        }
#pragma unroll
        for (int w = 1; w < 4; w <<= 1) {
            ls0 += __shfl_xor_sync(0xffffffffu, ls0, w);
            ls1 += __shfl_xor_sync(0xffffffffu, ls1, w);
        }
        rs0 = rs0 * al0 + ls0;
        rs1 = rs1 * al1 + ls1;
        m0r = mn0; m1r = mn1;
#pragma unroll
        for (int t = 0; t < 8; t++) {
            o[t][0] *= al0; o[t][1] *= al0;
            o[t][2] *= al1; o[t][3] *= al1;
        }

#pragma unroll
        for (int kk = 0; kk < 4; kk++) {
            uint32_t bv[8][2];
#pragma unroll
            for (int p = 0; p < 4; p++) {
                uint32_t r[4];
                ldmx4t(r, sV + bV_off + kk * (16 * 144) + p * 32);
                bv[p * 2][0] = r[0]; bv[p * 2][1] = r[1];
                bv[p * 2 + 1][0] = r[2]; bv[p * 2 + 1][1] = r[3];
            }
#pragma unroll
            for (int t = 0; t < 8; t++)
                mma16816(o[t], pa[kk], bv[t]);
        }
    }

    // epilogue: normalize, fp16 hi only into g_ah
    const float ri0 = 1.f / rs0, ri1 = 1.f / rs1;
    const size_t mrow0 = (size_t)b * S_LEN + qs + mbase + r0;
    __half* row0 = g_ah + mrow0 * D_MODEL;
    __half* row1 = row0 + (size_t)8 * D_MODEL;
    const int kc = h * HD + qcol;
#pragma unroll
    for (int t = 0; t < 8; t++) {
        const int k = kc + t * 8;
        *(uint32_t*)&row0[k] = h2pack(o[t][0] * ri0, o[t][1] * ri0);
        *(uint32_t*)&row1[k] = h2pack(o[t][2] * ri1, o[t][3] * ri1);
    }
}

// ---------------------------------------------------------------------------
extern "C" void kernel_launch(void* const* d_in, const int* in_sizes, int n_in,
                              void* d_out, int out_size)
{
    const float* x      = (const float*)d_in[0];
    const float* w_attn = (const float*)d_in[1];
    const float* b_attn = (const float*)d_in[2];
    const float* w_proj = (const float*)d_in[3];
    const float* b_proj = (const float*)d_in[4];
    float* out = (float*)d_out;
    float* kv  = out + OUT_ELEMS;

    cudaFuncSetAttribute(attn_k, cudaFuncAttributeMaxDynamicSharedMemorySize, ATTN_SMEM_BYTES);
    cudaFuncSetAttribute(gemm_mma<0>, cudaFuncAttributeMaxDynamicSharedMemorySize, GEMM_SMEM);
    cudaFuncSetAttribute(gemm_mma<1>, cudaFuncAttributeMaxDynamicSharedMemorySize, GEMM_SMEM);

    __half *xh, *ah, *wat, *wpt;
    cudaGetSymbolAddress((void**)&xh,  g_xh);
    cudaGetSymbolAddress((void**)&ah,  g_ah);
    cudaGetSymbolAddress((void**)&wat, g_wat);
    cudaGetSymbolAddress((void**)&wpt, g_wpt);

    // 1) conversions: x, w_attn^T, w_proj^T -> fp16 hi
    convAh_k<<<(TOKENS * 256 + 255) / 256, 256>>>(x, xh, TOKENS * 256);
    {
        dim3 blk(8, 32);
        convBth_k<<<dim3(3 * D_MODEL / 32, D_MODEL / 32), blk>>>(w_attn, wat, 3 * D_MODEL);
        convBth_k<<<dim3(D_MODEL / 32, D_MODEL / 32),     blk>>>(w_proj, wpt, D_MODEL);
    }

    // 2) QKV projection (K=1024): fp16 Q/K/V + fp32 present tail
    gemm_mma<1><<<dim3(3 * D_MODEL / 128, TOKENS / 128), 256, GEMM_SMEM>>>(
        xh, wat, b_attn, nullptr, kv);

    // 3) tensor-core flash attention -> g_ah (fp16 hi)
    attn_k<<<BATCH * NH * (S_LEN / 64), 128, ATTN_SMEM_BYTES>>>();

    // 4) output projection (K=1024) -> d_out head
    gemm_mma<0><<<dim3(D_MODEL / 128, TOKENS / 128), 256, GEMM_SMEM>>>(
        ah, wpt, b_proj, out, nullptr);
}